// round 12
// baseline (speedup 1.0000x reference)
#include <cuda_runtime.h>
#include <cuda_bf16.h>
#include <cuda_fp16.h>
#include <math.h>
#include <stdint.h>

#define Bz 8
#define BL 8192

__device__ __forceinline__ uint32_t smem_u32(const void* p) {
    uint32_t a;
    asm("{ .reg .u64 t; cvta.to.shared.u64 t, %1; cvt.u32.u64 %0, t; }" : "=r"(a) : "l"(p));
    return a;
}
__device__ __forceinline__ void cp16(uint32_t s, const void* g) {
    unsigned long long ga = (unsigned long long)__cvta_generic_to_global(g);
    asm volatile("cp.async.cg.shared.global [%0], [%1], 16;" :: "r"(s), "l"(ga));
}
__device__ __forceinline__ void ldsm4(uint32_t* r, uint32_t a) {
    asm volatile("ldmatrix.sync.aligned.m8n8.x4.shared.b16 {%0,%1,%2,%3}, [%4];"
                 : "=r"(r[0]), "=r"(r[1]), "=r"(r[2]), "=r"(r[3]) : "r"(a));
}
__device__ __forceinline__ void mma16816(float* c, const uint32_t* a, const uint32_t* b) {
    asm volatile("mma.sync.aligned.m16n8k16.row.col.f32.bf16.bf16.f32 "
                 "{%0,%1,%2,%3}, {%4,%5,%6,%7}, {%8,%9}, {%0,%1,%2,%3};"
                 : "+f"(c[0]), "+f"(c[1]), "+f"(c[2]), "+f"(c[3])
                 : "r"(a[0]), "r"(a[1]), "r"(a[2]), "r"(a[3]), "r"(b[0]), "r"(b[1]));
}
__device__ __forceinline__ void mmaf16(float* c, const uint32_t* a, const uint32_t* b) {
    asm volatile("mma.sync.aligned.m16n8k16.row.col.f32.f16.f16.f32 "
                 "{%0,%1,%2,%3}, {%4,%5,%6,%7}, {%8,%9}, {%0,%1,%2,%3};"
                 : "+f"(c[0]), "+f"(c[1]), "+f"(c[2]), "+f"(c[3])
                 : "r"(a[0]), "r"(a[1]), "r"(a[2]), "r"(a[3]), "r"(b[0]), "r"(b[1]));
}
__device__ __forceinline__ void bsplit(float v, __nv_bfloat16& h, __nv_bfloat16& l) {
    h = __float2bfloat16(v);
    l = __float2bfloat16(v - __bfloat162float(h));
}

// ---------------- scratch ----------------
#define AL __align__(256)
__device__ AL __nv_bfloat16 g_W1h[384*1024], g_W1l[384*1024];
__device__ float g_b1[384];
__device__ AL __nv_bfloat16 g_X1h[8192*1024], g_X1l[8192*1024];
__device__ float g_P1[384*8192];
__device__ AL __half g_Pp16[(size_t)64*1024*1024];
__device__ AL __half g_vTp16[64*32*1024];
__device__ float g_PV[64*32*1024];
__device__ AL __half g_Wo16[256*2304];
__device__ AL __half g_I216[8*34*34*256];
__device__ float g_O2[256*8192];
__device__ AL __half g_qc16[8*2048*1024], g_kc16[8*2048*1024];
__device__ float g_vc[8*2048*1024];
__device__ AL __half g_vT16[64*1024*256];
__device__ float g_Sc[64*256*256];
__device__ AL __half g_Pc16[64*256*256];
__device__ float g_oc[8*2048*1024];
__device__ AL __half g_Wf16[256*4608];
__device__ AL __half g_I316[8*66*66*512];

#define PITCHB 80
#define TSZ 10240

// ========= bf16 3-term GEMM (projection only; 128x128; 8 warps, 2-stage) =========
#define STGSZ 40960
#define TSMEM (2*STGSZ)
__global__ __launch_bounds__(256) void tgemm(
    const __nv_bfloat16* __restrict__ Ah, const __nv_bfloat16* __restrict__ Al,
    const __nv_bfloat16* __restrict__ Bh, const __nv_bfloat16* __restrict__ Bl,
    float* __restrict__ C, const float* __restrict__ bias, int N, int K)
{
    extern __shared__ __align__(128) char smem_raw[];
    const uint32_t sb = smem_u32(smem_raw);
    const int tid = threadIdx.x, wid = tid >> 5, lane = tid & 31;
    const int wm = wid >> 2, wn = wid & 3;
    const int m0 = blockIdx.y * 128, n0 = blockIdx.x * 128;

    const __nv_bfloat16* gp[4] = { Ah + (long)m0 * K, Al + (long)m0 * K,
                                   Bh + (long)n0 * K, Bl + (long)n0 * K };
    const int lg = lane >> 3, l8 = lane & 7;
    const int row_off = l8 + (lg & 1) * 8;
    const int kadd = (lg >> 1) * 8;
    const int rowA = wm * 64 + row_off;
    const int rowB = wn * 32 + row_off;

    float acc[4][4][4];
#pragma unroll
    for (int a = 0; a < 4; a++)
#pragma unroll
        for (int b = 0; b < 4; b++)
#pragma unroll
            for (int c = 0; c < 4; c++) acc[a][b][c] = 0.f;

    const int nch = K >> 5;
    auto load_stage = [&](int ch, int st) {
        uint32_t base = sb + st * STGSZ;
        int k0 = ch << 5;
#pragma unroll
        for (int j = 0; j < 8; j++) {
            int id = tid + j * 256;
            int t = id >> 9, w = id & 511;
            int row = w >> 2, c16 = (w & 3);
            cp16(base + t * TSZ + row * PITCHB + c16 * 16,
                 gp[t] + (long)row * K + k0 + c16 * 8);
        }
        asm volatile("cp.async.commit_group;" ::: "memory");
    };

    load_stage(0, 0);
    for (int i = 0; i < nch; i++) {
        int st = i & 1;
        if (i + 1 < nch) { load_stage(i + 1, st ^ 1);
            asm volatile("cp.async.wait_group 1;" ::: "memory");
        } else asm volatile("cp.async.wait_group 0;" ::: "memory");
        __syncthreads();
        uint32_t sA_h = sb + st * STGSZ, sA_l = sA_h + TSZ;
        uint32_t sB_h = sA_h + 2 * TSZ, sB_l = sA_h + 3 * TSZ;
#pragma unroll
        for (int ks = 0; ks < 2; ks++) {
            uint32_t kb = (uint32_t)(ks * 16 + kadd) * 2;
            uint32_t bh[4][2], bl[4][2];
#pragma unroll
            for (int p = 0; p < 2; p++) {
                uint32_t r[4];
                ldsm4(r, sB_h + (uint32_t)(rowB + p * 16) * PITCHB + kb);
                bh[p*2][0] = r[0]; bh[p*2][1] = r[2];
                bh[p*2+1][0] = r[1]; bh[p*2+1][1] = r[3];
                ldsm4(r, sB_l + (uint32_t)(rowB + p * 16) * PITCHB + kb);
                bl[p*2][0] = r[0]; bl[p*2][1] = r[2];
                bl[p*2+1][0] = r[1]; bl[p*2+1][1] = r[3];
            }
#pragma unroll
            for (int mt = 0; mt < 4; mt++) {
                uint32_t ah[4], al[4];
                ldsm4(ah, sA_h + (uint32_t)(rowA + mt * 16) * PITCHB + kb);
                ldsm4(al, sA_l + (uint32_t)(rowA + mt * 16) * PITCHB + kb);
#pragma unroll
                for (int nt = 0; nt < 4; nt++) {
                    mma16816(acc[mt][nt], ah, bh[nt]);
                    mma16816(acc[mt][nt], ah, bl[nt]);
                    mma16816(acc[mt][nt], al, bh[nt]);
                }
            }
        }
        __syncthreads();
    }
#pragma unroll
    for (int mt = 0; mt < 4; mt++) {
        int m = m0 + wm * 64 + mt * 16 + (lane >> 2);
        float b0 = bias[m], b1 = bias[m + 8];
#pragma unroll
        for (int nt = 0; nt < 4; nt++) {
            int n = n0 + wn * 32 + nt * 8 + (lane & 3) * 2;
            float2 v0 = { acc[mt][nt][0] + b0, acc[mt][nt][1] + b0 };
            float2 v1 = { acc[mt][nt][2] + b1, acc[mt][nt][3] + b1 };
            *(float2*)(C + (long)m * N + n) = v0;
            *(float2*)(C + (long)(m + 8) * N + n) = v1;
        }
    }
}

// ========= fp16 single-term GEMM: 128x256 tile, 8 warps (2x4 of 64x64) =========
#define ASZ 10240
#define BSZ 20480
#define STG256 30720
#define TSMEM256 (2*STG256)

#define F16_COMPUTE(sA2, sB2)                                                  \
    _Pragma("unroll")                                                          \
    for (int ks = 0; ks < 2; ks++) {                                           \
        uint32_t kb = (uint32_t)(ks * 16 + kadd) * 2;                          \
        uint32_t bf[8][2];                                                     \
        _Pragma("unroll")                                                      \
        for (int p = 0; p < 4; p++) {                                          \
            uint32_t r[4];                                                     \
            ldsm4(r, (sB2) + (uint32_t)(rowB + p * 16) * PITCHB + kb);         \
            bf[p*2][0] = r[0]; bf[p*2][1] = r[2];                              \
            bf[p*2+1][0] = r[1]; bf[p*2+1][1] = r[3];                          \
        }                                                                      \
        _Pragma("unroll")                                                      \
        for (int mt = 0; mt < 4; mt++) {                                       \
            uint32_t af[4];                                                    \
            ldsm4(af, (sA2) + (uint32_t)(rowA + mt * 16) * PITCHB + kb);       \
            _Pragma("unroll")                                                  \
            for (int nt = 0; nt < 8; nt++) mmaf16(acc[mt][nt], af, bf[nt]);    \
        }                                                                      \
    }

__global__ __launch_bounds__(256) void tgemm16(
    const __half* __restrict__ A, const __half* __restrict__ B,
    float* __restrict__ C, int N, int K, long sA, long sB, long sC)
{
    extern __shared__ __align__(128) char smem_raw[];
    const uint32_t sb = smem_u32(smem_raw);
    const int tid = threadIdx.x, wid = tid >> 5, lane = tid & 31;
    const int wm = wid >> 2, wn = wid & 3;
    const int m0 = blockIdx.y * 128, n0 = blockIdx.x * 256;
    const __half* pA = A + (long)blockIdx.z * sA + (long)m0 * K;
    const __half* pB = B + (long)blockIdx.z * sB + (long)n0 * K;
    const int lg = lane >> 3, l8 = lane & 7;
    const int row_off = l8 + (lg & 1) * 8;
    const int kadd = (lg >> 1) * 8;
    const int rowA = wm * 64 + row_off;
    const int rowB = wn * 64 + row_off;

    float acc[4][8][4];
#pragma unroll
    for (int a = 0; a < 4; a++)
#pragma unroll
        for (int b = 0; b < 8; b++)
#pragma unroll
            for (int c = 0; c < 4; c++) acc[a][b][c] = 0.f;

    const int nch = K >> 5;
    auto load_stage = [&](int ch, int st) {
        uint32_t base = sb + st * STG256;
        int k0 = ch << 5;
#pragma unroll
        for (int j = 0; j < 6; j++) {
            int id = tid + j * 256;
            if (id < 512) {
                int row = id >> 2, c16 = id & 3;
                cp16(base + row * PITCHB + c16 * 16, pA + (long)row * K + k0 + c16 * 8);
            } else {
                int w = id - 512;
                int row = w >> 2, c16 = w & 3;
                cp16(base + ASZ + row * PITCHB + c16 * 16, pB + (long)row * K + k0 + c16 * 8);
            }
        }
        asm volatile("cp.async.commit_group;" ::: "memory");
    };

    load_stage(0, 0);
    for (int i = 0; i < nch; i++) {
        int st = i & 1;
        if (i + 1 < nch) { load_stage(i + 1, st ^ 1);
            asm volatile("cp.async.wait_group 1;" ::: "memory");
        } else asm volatile("cp.async.wait_group 0;" ::: "memory");
        __syncthreads();
        uint32_t sA2 = sb + st * STG256, sB2 = sA2 + ASZ;
        F16_COMPUTE(sA2, sB2)
        __syncthreads();
    }
    float* Cb = C + (long)blockIdx.z * sC;
#pragma unroll
    for (int mt = 0; mt < 4; mt++) {
        int m = m0 + wm * 64 + mt * 16 + (lane >> 2);
#pragma unroll
        for (int nt = 0; nt < 8; nt++) {
            int n = n0 + wn * 64 + nt * 8 + (lane & 3) * 2;
            *(float2*)(Cb + (long)m * N + n) = *(float2*)&acc[mt][nt][0];
            *(float2*)(Cb + (long)(m + 8) * N + n) = *(float2*)&acc[mt][nt][2];
        }
    }
}

// ========= fp16 direct-conv GEMM (128x256 tile) =========
template<int LW, int CH, int PW, bool DIRECT>
__global__ __launch_bounds__(256) void tgemm_conv16(
    const __half* __restrict__ A, const __half* __restrict__ I,
    float* __restrict__ C, const float* __restrict__ bias, int N, int K)
{
    extern __shared__ __align__(128) char smem_raw[];
    const uint32_t sb = smem_u32(smem_raw);
    const int tid = threadIdx.x, wid = tid >> 5, lane = tid & 31;
    const int wm = wid >> 2, wn = wid & 3;
    const int m0 = blockIdx.y * 128, n0 = blockIdx.x * 256;
    const __half* pA = A + (long)m0 * K;
    constexpr int CPT = CH / 32;
    const int lg = lane >> 3, l8 = lane & 7;
    const int row_off = l8 + (lg & 1) * 8;
    const int kadd = (lg >> 1) * 8;
    const int rowA = wm * 64 + row_off;
    const int rowB = wn * 64 + row_off;

    float acc[4][8][4];
#pragma unroll
    for (int a = 0; a < 4; a++)
#pragma unroll
        for (int b = 0; b < 8; b++)
#pragma unroll
            for (int c = 0; c < 4; c++) acc[a][b][c] = 0.f;

    const int nch = K >> 5;
    auto load_stage = [&](int ch, int st) {
        uint32_t base = sb + st * STG256;
        int k0 = ch << 5;
        int tap = ch / CPT;
        int cc0 = (ch % CPT) << 5;
        int dyp = tap / 3, dxp = tap - dyp * 3;
#pragma unroll
        for (int j = 0; j < 6; j++) {
            int id = tid + j * 256;
            if (id < 512) {
                int row = id >> 2, c16 = id & 3;
                cp16(base + row * PITCHB + c16 * 16, pA + (long)row * K + k0 + c16 * 8);
            } else {
                int w = id - 512;
                int row = w >> 2, c16 = w & 3;
                int n = n0 + row;
                int b = n >> (2 * LW);
                int pix = n & ((1 << (2 * LW)) - 1);
                int Y = pix >> LW, X = pix & ((1 << LW) - 1);
                long off = ((long)((b * PW + Y + dyp) * PW) + X + dxp) * CH + cc0 + c16 * 8;
                cp16(base + ASZ + row * PITCHB + c16 * 16, I + off);
            }
        }
        asm volatile("cp.async.commit_group;" ::: "memory");
    };

    load_stage(0, 0);
    for (int i = 0; i < nch; i++) {
        int st = i & 1;
        if (i + 1 < nch) { load_stage(i + 1, st ^ 1);
            asm volatile("cp.async.wait_group 1;" ::: "memory");
        } else asm volatile("cp.async.wait_group 0;" ::: "memory");
        __syncthreads();
        uint32_t sA2 = sb + st * STG256, sB2 = sA2 + ASZ;
        F16_COMPUTE(sA2, sB2)
        __syncthreads();
    }
#pragma unroll
    for (int mt = 0; mt < 4; mt++) {
        int m = m0 + wm * 64 + mt * 16 + (lane >> 2);
        float b0 = bias[m], b1 = bias[m + 8];
#pragma unroll
        for (int nt = 0; nt < 8; nt++) {
            int n = n0 + wn * 64 + nt * 8 + (lane & 3) * 2;
            float2 v0 = { acc[mt][nt][0] + b0, acc[mt][nt][1] + b0 };
            float2 v1 = { acc[mt][nt][2] + b1, acc[mt][nt][3] + b1 };
            if (DIRECT) {
                long base0 = ((long)(n >> 12) << 20) + (n & 4095);
                *(float2*)(C + base0 + (long)m * 4096) = v0;
                *(float2*)(C + base0 + (long)(m + 8) * 4096) = v1;
            } else {
                *(float2*)(C + (long)m * N + n) = v0;
                *(float2*)(C + (long)(m + 8) * N + n) = v1;
            }
        }
    }
}

// ========= fp16 PV GEMM (unchanged) =========
#define PVATSZ 2560
#define PVBTSZ 20480
#define PVSTG16 (PVATSZ + PVBTSZ)
#define PVSMEM16 (2*PVSTG16)
__global__ __launch_bounds__(256) void tgemm_pv16()
{
    extern __shared__ __align__(128) char smem_raw[];
    const uint32_t sb = smem_u32(smem_raw);
    const int tid = threadIdx.x, wid = tid >> 5, lane = tid & 31;
    const int n0 = blockIdx.x * 256;
    const int z = blockIdx.z;
    const __half* pA = g_vTp16 + (long)z * 32768;
    const __half* pB = g_Pp16 + (size_t)z * 1048576;
    const int lg = lane >> 3, l8 = lane & 7;
    const int row_off = l8 + (lg & 1) * 8;
    const int kadd = (lg >> 1) * 8;
    const int rowB = wid * 32 + row_off;

    float acc[2][4][4];
#pragma unroll
    for (int a = 0; a < 2; a++)
#pragma unroll
        for (int b = 0; b < 4; b++)
#pragma unroll
            for (int c = 0; c < 4; c++) acc[a][b][c] = 0.f;

    auto load_stage = [&](int ch, int st) {
        uint32_t base = sb + st * PVSTG16;
        int k0 = ch << 5;
#pragma unroll
        for (int j = 0; j < 5; j++) {
            int id = tid + j * 256;
            if (id < 128) {
                int row = id >> 2, c16 = id & 3;
                cp16(base + row * PITCHB + c16 * 16, pA + (long)row * 1024 + k0 + c16 * 8);
            } else if (id < 1152) {
                int w = id - 128;
                int row = w >> 2, c16 = w & 3;
                cp16(base + PVATSZ + row * PITCHB + c16 * 16,
                     pB + (long)(n0 + row) * 1024 + k0 + c16 * 8);
            }
        }
        asm volatile("cp.async.commit_group;" ::: "memory");
    };

    load_stage(0, 0);
    for (int i = 0; i < 32; i++) {
        int st = i & 1;
        if (i + 1 < 32) { load_stage(i + 1, st ^ 1);
            asm volatile("cp.async.wait_group 1;" ::: "memory");
        } else asm volatile("cp.async.wait_group 0;" ::: "memory");
        __syncthreads();
        uint32_t sA2 = sb + st * PVSTG16, sB2 = sA2 + PVATSZ;
#pragma unroll
        for (int ks = 0; ks < 2; ks++) {
            uint32_t kb = (uint32_t)(ks * 16 + kadd) * 2;
            uint32_t bf[4][2];
#pragma unroll
            for (int p = 0; p < 2; p++) {
                uint32_t r[4];
                ldsm4(r, sB2 + (uint32_t)(rowB + p * 16) * PITCHB + kb);
                bf[p*2][0] = r[0]; bf[p*2][1] = r[2];
                bf[p*2+1][0] = r[1]; bf[p*2+1][1] = r[3];
            }
#pragma unroll
            for (int mt = 0; mt < 2; mt++) {
                uint32_t af[4];
                ldsm4(af, sA2 + (uint32_t)(row_off + mt * 16) * PITCHB + kb);
#pragma unroll
                for (int nt = 0; nt < 4; nt++) mmaf16(acc[mt][nt], af, bf[nt]);
            }
        }
        __syncthreads();
    }
    float* Cb = g_PV + (long)z * 32768;
#pragma unroll
    for (int mt = 0; mt < 2; mt++) {
        int m = mt * 16 + (lane >> 2);
#pragma unroll
        for (int nt = 0; nt < 4; nt++) {
            int n = n0 + wid * 32 + nt * 8 + (lane & 3) * 2;
            *(float2*)(Cb + (long)m * 1024 + n) = *(float2*)&acc[mt][nt][0];
            *(float2*)(Cb + (long)(m + 8) * 1024 + n) = *(float2*)&acc[mt][nt][2];
        }
    }
}

// ---------------- reduce helpers ----------------
__device__ __forceinline__ float wmax(float v) {
#pragma unroll
    for (int o = 16; o; o >>= 1) v = fmaxf(v, __shfl_xor_sync(~0u, v, o));
    return v;
}
__device__ __forceinline__ float wsum(float v) {
#pragma unroll
    for (int o = 16; o; o >>= 1) v += __shfl_xor_sync(~0u, v, o);
    return v;
}

// ---------------- small kernels ----------------
__global__ void k_zero4(float4* p, int n4) {
    int i = blockIdx.x * 256 + threadIdx.x;
    if (i < n4) p[i] = make_float4(0.f, 0.f, 0.f, 0.f);
}
__global__ void k_wrd16(const float* __restrict__ W, __half* __restrict__ h, int CIN) {
    int idx = blockIdx.x * 256 + threadIdx.x;
    int K = CIN * 9;
    int oc = idx / K, rem = idx - oc * K;
    int cc = rem / 9, tap = rem - cc * 9;
    h[(long)oc * K + tap * CIN + cc] = __float2half(W[idx]);
}
__global__ void k_pack_w1(const float* __restrict__ Wq, const float* __restrict__ bq,
                          const float* __restrict__ Wk, const float* __restrict__ bk,
                          const float* __restrict__ Wv, const float* __restrict__ bv) {
    int idx = blockIdx.x * 256 + threadIdx.x;
    float v;
    if (idx < 65536) v = Wq[idx];
    else if (idx < 131072) v = Wk[idx - 65536];
    else v = Wv[idx - 131072];
    __nv_bfloat16 a, b; bsplit(v, a, b);
    g_W1h[idx] = a; g_W1l[idx] = b;
    if (idx < 64) g_b1[idx] = bq[idx];
    else if (idx < 128) g_b1[idx] = bk[idx - 64];
    else if (idx < 384) g_b1[idx] = bv[idx - 128];
}
__global__ void k_im2col1(const float* __restrict__ x) {
    __shared__ float t[32][33];
    int k0 = blockIdx.x * 32, n0 = blockIdx.y * 32;
    int tx = threadIdx.x;
#pragma unroll
    for (int it = 0; it < 4; it++) {
        int ty = threadIdx.y + it * 8;
        int k = k0 + ty, n = n0 + tx;
        int c = k >> 2, ky = (k >> 1) & 1, kx = k & 1;
        int b = n >> 10, l = n & 1023, y = l >> 5, xq = l & 31;
        t[ty][tx] = x[(((b * 256 + c) * 64) + (y * 2 + ky)) * 64 + xq * 2 + kx];
    }
    __syncthreads();
#pragma unroll
    for (int it = 0; it < 4; it++) {
        int ty = threadIdx.y + it * 8;
        __nv_bfloat16 a, b; bsplit(t[tx][ty], a, b);
        long o = (long)(n0 + ty) * 1024 + k0 + tx;
        g_X1h[o] = a; g_X1l[o] = b;
    }
}
__global__ void k_pos_attn() {
    __shared__ float Ks[8][1024];
    int b = blockIdx.z, h = blockIdx.y, tid = threadIdx.x;
    for (int idx = tid; idx < 8192; idx += 256) {
        int d = idx >> 10, k = idx & 1023;
        Ks[d][k] = g_P1[(64 + h * 8 + d) * BL + b * 1024 + k];
    }
    __syncthreads();
    int warp = tid >> 5, lane = tid & 31;
    int qb = blockIdx.x * 64 + warp * 8;
#pragma unroll 1
    for (int qq = 0; qq < 8; qq++) {
        int q = qb + qq;
        float Q[8];
#pragma unroll
        for (int d = 0; d < 8; d++) Q[d] = g_P1[(h * 8 + d) * BL + b * 1024 + q];
        float s[32], mx = -1e30f;
#pragma unroll
        for (int i = 0; i < 32; i++) {
            int k = i * 32 + lane;
            float sc = 0.f;
#pragma unroll
            for (int d = 0; d < 8; d++) sc += Q[d] * Ks[d][k];
            sc *= 0.35355339059327373f;
            s[i] = sc; mx = fmaxf(mx, sc);
        }
        mx = wmax(mx);
        float sum = 0.f;
#pragma unroll
        for (int i = 0; i < 32; i++) { float e = __expf(s[i] - mx); s[i] = e; sum += e; }
        float inv = 1.0f / wsum(sum);
        size_t ob = ((size_t)(b * 8 + h) * 1024 + q) * 1024 + lane;
#pragma unroll
        for (int i = 0; i < 32; i++) g_Pp16[ob + i * 32] = __float2half(s[i] * inv);
    }
}
__global__ void k_vtp() {
    int idx = blockIdx.x * 256 + threadIdx.x;
    int k = idx & 1023, d = (idx >> 10) & 31, bh = idx >> 15;
    g_vTp16[idx] = __float2half(g_P1[(128 + (bh & 7) * 32 + d) * BL + (bh >> 3) * 1024 + k]);
}
__global__ void k_o1t() {
    __shared__ float t[32][33];
    int q0 = blockIdx.x * 32, z = blockIdx.y;
    int b = z >> 3, h = z & 7;
    int tx = threadIdx.x;
#pragma unroll
    for (int it = 0; it < 4; it++) {
        int ty = threadIdx.y + it * 8;
        t[ty][tx] = g_PV[((long)z * 32 + ty) * 1024 + q0 + tx];
    }
    __syncthreads();
#pragma unroll
    for (int it = 0; it < 4; it++) {
        int ty = threadIdx.y + it * 8;
        int q = q0 + ty;
        int y = q >> 5, x = q & 31;
        long o = ((long)(b * 34 + 1 + y) * 34 + 1 + x) * 256 + h * 32 + tx;
        g_I216[o] = __float2half(t[tx][ty]);
    }
}
__global__ void k_cha_proj(const float* __restrict__ x,
                           const float* __restrict__ Wq, const float* __restrict__ bq,
                           const float* __restrict__ Wk, const float* __restrict__ bk,
                           const float* __restrict__ Wv, const float* __restrict__ bv) {
    int l = blockIdx.x * 256 + threadIdx.x;
    int g = blockIdx.y, b = blockIdx.z;
    int i = l >> 5, j = l & 31;
    const float* xp = x + ((b * 256 + g) * 64) * 64;
    float x00 = xp[2*i*64 + 2*j], x01 = xp[2*i*64 + 2*j + 1];
    float x10 = xp[(2*i+1)*64 + 2*j], x11 = xp[(2*i+1)*64 + 2*j + 1];
    int base = (b * 2048 + g * 8) * 1024 + l;
#pragma unroll
    for (int h = 0; h < 8; h++) {
        int w = (g * 8 + h) * 4, o = base + h * 1024;
        float qv = Wq[w]*x00 + Wq[w+1]*x01 + Wq[w+2]*x10 + Wq[w+3]*x11 + bq[g*8+h];
        float kv = Wk[w]*x00 + Wk[w+1]*x01 + Wk[w+2]*x10 + Wk[w+3]*x11 + bk[g*8+h];
        float vv = Wv[w]*x00 + Wv[w+1]*x01 + Wv[w+2]*x10 + Wv[w+3]*x11 + bv[g*8+h];
        g_qc16[o] = __float2half(qv);
        g_kc16[o] = __float2half(kv);
        g_vc[o] = vv;
    }
}
__global__ void k_vcT() {
    __shared__ float t[32][33];
    int z = blockIdx.z, c0 = blockIdx.x * 32, l0 = blockIdx.y * 32;
    int tx = threadIdx.x;
    const float* src = g_vc + (long)z * 262144;
#pragma unroll
    for (int it = 0; it < 4; it++) {
        int ty = threadIdx.y + it * 8;
        t[ty][tx] = src[(c0 + ty) * 1024 + l0 + tx];
    }
    __syncthreads();
#pragma unroll
    for (int it = 0; it < 4; it++) {
        int ty = threadIdx.y + it * 8;
        long o = (long)z * 262144 + (long)(l0 + ty) * 256 + c0 + tx;
        g_vT16[o] = __float2half(t[tx][ty]);
    }
}
__global__ void k_cha_softmax() {
    int row = blockIdx.x * 8 + (threadIdx.x >> 5);
    int lane = threadIdx.x & 31;
    const float* r = g_Sc + (long)row * 256;
    float v[8], mx = -1e30f;
#pragma unroll
    for (int j = 0; j < 8; j++) { v[j] = r[j * 32 + lane] * 0.03125f; mx = fmaxf(mx, v[j]); }
    mx = wmax(mx);
    float sum = 0.f;
#pragma unroll
    for (int j = 0; j < 8; j++) { v[j] = __expf(v[j] - mx); sum += v[j]; }
    float inv = 1.0f / wsum(sum);
#pragma unroll
    for (int j = 0; j < 8; j++)
        g_Pc16[(long)row * 256 + j * 32 + lane] = __float2half(v[j] * inv);
}
__global__ void k_fusepack(const float* __restrict__ xp_, const float* __restrict__ xc_,
                           const float* __restrict__ Wt, const float* __restrict__ bt,
                           const float* __restrict__ gp_, const float* __restrict__ gc_) {
    __shared__ float t[32][33];
    int c0 = blockIdx.x * 32, p0 = blockIdx.y * 32, b = blockIdx.z;
    int tx = threadIdx.x;
    float gp = gp_[0], gc = gc_[0];
#pragma unroll
    for (int it = 0; it < 4; it++) {
        int ty = threadIdx.y + it * 8;
        int c = c0 + ty, pix = p0 + tx;
        int Y = pix >> 6, X = pix & 63;
        float v;
        if (c < 256) {
            float sy = Y * 0.5f - 0.25f, sx = X * 0.5f - 0.25f;
            int y0 = (int)floorf(sy); float fy = sy - y0;
            int x0 = (int)floorf(sx); float fx = sx - x0;
            int y1 = min(y0 + 1, 31); y0 = max(y0, 0);
            int x1 = min(x0 + 1, 31); x0 = max(x0, 0);
            const float* p = g_O2 + c * 8192 + b * 1024;
            float u = (1.f - fy) * ((1.f - fx) * p[y0*32+x0] + fx * p[y0*32+x1])
                    + fy * ((1.f - fx) * p[y1*32+x0] + fx * p[y1*32+x1]);
            v = xp_[((b * 256 + c) * 4096) + pix] + gp * u;
        } else {
            int g = c - 256;
            int pp = Y >> 1, ky = Y & 1, qq = X >> 1, kx = X & 1;
            float s = bt[g];
            int ob = (b * 2048 + g * 8) * 1024 + pp * 32 + qq;
#pragma unroll
            for (int i = 0; i < 8; i++)
                s += g_oc[ob + i * 1024] * Wt[(g * 8 + i) * 4 + ky * 2 + kx];
            v = xc_[((b * 256 + g) * 4096) + pix] + gc * s;
        }
        t[ty][tx] = v;
    }
    __syncthreads();
#pragma unroll
    for (int it = 0; it < 4; it++) {
        int ty = threadIdx.y + it * 8;
        int pix = p0 + ty, c = c0 + tx;
        int Y = pix >> 6, X = pix & 63;
        long o = ((long)(b * 66 + 1 + Y) * 66 + 1 + X) * 512 + c;
        g_I316[o] = __float2half(t[tx][ty]);
    }
}

// ---------------- launch ----------------
static void* sym(const void* s) { void* p = nullptr; cudaGetSymbolAddress(&p, s); return p; }

extern "C" void kernel_launch(void* const* d_in, const int* in_sizes, int n_in,
                              void* d_out, int out_size) {
    const float *qkv_pos = (const float*)d_in[0], *qkv_cha = (const float*)d_in[1];
    const float *Wq_pos = (const float*)d_in[2], *bq_pos = (const float*)d_in[3];
    const float *Wk_pos = (const float*)d_in[4], *bk_pos = (const float*)d_in[5];
    const float *Wv_pos = (const float*)d_in[6], *bv_pos = (const float*)d_in[7];
    const float *Wo_pos = (const float*)d_in[8], *bo_pos = (const float*)d_in[9];
    const float *gamma_pos = (const float*)d_in[10];
    const float *Wq_cha = (const float*)d_in[11], *bq_cha = (const float*)d_in[12];
    const float *Wk_cha = (const float*)d_in[13], *bk_cha = (const float*)d_in[14];
    const float *Wv_cha = (const float*)d_in[15], *bv_cha = (const float*)d_in[16];
    const float *Wt_cha = (const float*)d_in[17], *bt_cha = (const float*)d_in[18];
    const float *gamma_cha = (const float*)d_in[19];
    const float *Wf = (const float*)d_in[20], *bf = (const float*)d_in[21];
    float* out = (float*)d_out;

    static cudaStream_t s1 = nullptr;
    static cudaEvent_t evF = nullptr, evJ = nullptr;
    if (!s1) {
        cudaStreamCreateWithFlags(&s1, cudaStreamNonBlocking);
        cudaEventCreateWithFlags(&evF, cudaEventDisableTiming);
        cudaEventCreateWithFlags(&evJ, cudaEventDisableTiming);
        cudaFuncSetAttribute(tgemm, cudaFuncAttributeMaxDynamicSharedMemorySize, TSMEM);
        cudaFuncSetAttribute(tgemm16, cudaFuncAttributeMaxDynamicSharedMemorySize, TSMEM256);
        cudaFuncSetAttribute(tgemm_conv16<5,256,34,false>, cudaFuncAttributeMaxDynamicSharedMemorySize, TSMEM256);
        cudaFuncSetAttribute(tgemm_conv16<6,512,66,true>, cudaFuncAttributeMaxDynamicSharedMemorySize, TSMEM256);
        cudaFuncSetAttribute(tgemm_pv16, cudaFuncAttributeMaxDynamicSharedMemorySize, PVSMEM16);
    }

    __nv_bfloat16 *pW1h = (__nv_bfloat16*)sym(g_W1h), *pW1l = (__nv_bfloat16*)sym(g_W1l);
    __nv_bfloat16 *pX1h = (__nv_bfloat16*)sym(g_X1h), *pX1l = (__nv_bfloat16*)sym(g_X1l);
    __half *pWo16 = (__half*)sym(g_Wo16), *pI216 = (__half*)sym(g_I216);
    __half *pWf16 = (__half*)sym(g_Wf16), *pI316 = (__half*)sym(g_I316);
    __half *pqc16 = (__half*)sym(g_qc16), *pkc16 = (__half*)sym(g_kc16);
    __half *pvT16 = (__half*)sym(g_vT16), *pPc16 = (__half*)sym(g_Pc16);
    float *pb1 = (float*)sym(g_b1), *pP1 = (float*)sym(g_P1);
    float *pO2 = (float*)sym(g_O2), *pSc = (float*)sym(g_Sc), *poc = (float*)sym(g_oc);

    // ---- fork: CHA branch + fusion prep on s1 ----
    cudaEventRecord(evF, 0);
    cudaStreamWaitEvent(s1, evF, 0);

    k_zero4<<<8712, 256, 0, s1>>>((float4*)pI316, 2230272 / 2);
    k_wrd16<<<4608, 256, 0, s1>>>(Wf, pWf16, 512);
    k_cha_proj<<<dim3(4, 256, 8), 256, 0, s1>>>(qkv_cha, Wq_cha, bq_cha, Wk_cha, bk_cha, Wv_cha, bv_cha);
    k_vcT<<<dim3(8, 32, 64), dim3(32, 8), 0, s1>>>();
    tgemm16<<<dim3(1, 2, 64), 256, TSMEM256, s1>>>(pqc16, pkc16, pSc, 256, 1024, 262144L, 262144L, 65536L);
    k_cha_softmax<<<2048, 256, 0, s1>>>();
    tgemm16<<<dim3(4, 2, 64), 256, TSMEM256, s1>>>(pPc16, pvT16, poc, 1024, 256, 65536L, 262144L, 262144L);
    cudaEventRecord(evJ, s1);

    // ---- POS branch on default stream ----
    k_pack_w1<<<1536, 256>>>(Wq_pos, bq_pos, Wk_pos, bk_pos, Wv_pos, bv_pos);
    k_im2col1<<<dim3(32, 256), dim3(32, 8)>>>(qkv_pos);
    k_zero4<<<578, 256>>>((float4*)pI216, 147968);
    tgemm<<<dim3(64, 3, 1), 256, TSMEM>>>(pW1h, pW1l, pX1h, pX1l, pP1, pb1, 8192, 1024);
    k_pos_attn<<<dim3(16, 8, 8), 256>>>();
    k_vtp<<<8192, 256>>>();
    tgemm_pv16<<<dim3(4, 1, 64), 256, PVSMEM16>>>();
    k_o1t<<<dim3(32, 64), dim3(32, 8)>>>();
    k_wrd16<<<2304, 256>>>(Wo_pos, pWo16, 256);
    tgemm_conv16<5,256,34,false><<<dim3(32, 2), 256, TSMEM256>>>(pWo16, pI216, pO2, bo_pos, 8192, 2304);

    // ---- join + fused residual/pack + fusion conv direct to out ----
    cudaStreamWaitEvent(0, evJ, 0);
    k_fusepack<<<dim3(16, 128, 8), dim3(32, 8)>>>(qkv_pos, qkv_cha, Wt_cha, bt_cha, gamma_pos, gamma_cha);
    tgemm_conv16<6,512,66,true><<<dim3(128, 2), 256, TSMEM256>>>(pWf16, pI316, out, bf, 32768, 4608);
}

// round 13
// speedup vs baseline: 1.0943x; 1.0943x over previous
#include <cuda_runtime.h>
#include <cuda_fp16.h>
#include <math.h>
#include <stdint.h>

#define Bz 8
#define BL 8192

__device__ __forceinline__ uint32_t smem_u32(const void* p) {
    uint32_t a;
    asm("{ .reg .u64 t; cvta.to.shared.u64 t, %1; cvt.u32.u64 %0, t; }" : "=r"(a) : "l"(p));
    return a;
}
__device__ __forceinline__ void cp16(uint32_t s, const void* g) {
    unsigned long long ga = (unsigned long long)__cvta_generic_to_global(g);
    asm volatile("cp.async.cg.shared.global [%0], [%1], 16;" :: "r"(s), "l"(ga));
}
__device__ __forceinline__ void ldsm4(uint32_t* r, uint32_t a) {
    asm volatile("ldmatrix.sync.aligned.m8n8.x4.shared.b16 {%0,%1,%2,%3}, [%4];"
                 : "=r"(r[0]), "=r"(r[1]), "=r"(r[2]), "=r"(r[3]) : "r"(a));
}
__device__ __forceinline__ void mmaf16(float* c, const uint32_t* a, const uint32_t* b) {
    asm volatile("mma.sync.aligned.m16n8k16.row.col.f32.f16.f16.f32 "
                 "{%0,%1,%2,%3}, {%4,%5,%6,%7}, {%8,%9}, {%0,%1,%2,%3};"
                 : "+f"(c[0]), "+f"(c[1]), "+f"(c[2]), "+f"(c[3])
                 : "r"(a[0]), "r"(a[1]), "r"(a[2]), "r"(a[3]), "r"(b[0]), "r"(b[1]));
}

// ---------------- scratch ----------------
#define AL __align__(256)
__device__ AL __half g_W116[384*1024];
__device__ float g_b1[384];
__device__ AL __half g_X116[8192*1024];
__device__ float g_P1[384*8192];
__device__ AL __half g_Pp16[(size_t)64*1024*1024];
__device__ AL __half g_vTp16[64*32*1024];
__device__ float g_PV[64*32*1024];
__device__ AL __half g_Wo16[256*2304];
__device__ AL __half g_I216[8*34*34*256];
__device__ float g_O2[256*8192];
__device__ AL __half g_qc16[8*2048*1024], g_kc16[8*2048*1024];
__device__ float g_vc[8*2048*1024];
__device__ AL __half g_vT16[64*1024*256];
__device__ float g_Sc[64*256*256];
__device__ AL __half g_Pc16[64*256*256];
__device__ float g_oc[8*2048*1024];
__device__ AL __half g_Wf16[256*4608];
__device__ AL __half g_I316[8*66*66*512];

#define PITCHB 80
#define TSZ 10240

// ========= fp16 single-term GEMM (128x128 tile, 8 warps, 2-stage) =========
#define STG16 20480
#define TSMEM16 (2*STG16)
__global__ __launch_bounds__(256) void tgemm16(
    const __half* __restrict__ A, const __half* __restrict__ B,
    float* __restrict__ C, const float* __restrict__ bias,
    int N, int K, long sA, long sB, long sC)
{
    extern __shared__ __align__(128) char smem_raw[];
    const uint32_t sb = smem_u32(smem_raw);
    const int tid = threadIdx.x, wid = tid >> 5, lane = tid & 31;
    const int wm = wid >> 2, wn = wid & 3;
    const int m0 = blockIdx.y * 128, n0 = blockIdx.x * 128;
    const __half* gp[2] = { A + (long)blockIdx.z * sA + (long)m0 * K,
                            B + (long)blockIdx.z * sB + (long)n0 * K };
    const int lg = lane >> 3, l8 = lane & 7;
    const int row_off = l8 + (lg & 1) * 8;
    const int kadd = (lg >> 1) * 8;
    const int rowA = wm * 64 + row_off;
    const int rowB = wn * 32 + row_off;

    float acc[4][4][4];
#pragma unroll
    for (int a = 0; a < 4; a++)
#pragma unroll
        for (int b = 0; b < 4; b++)
#pragma unroll
            for (int c = 0; c < 4; c++) acc[a][b][c] = 0.f;

    const int nch = K >> 5;
    auto load_stage = [&](int ch, int st) {
        uint32_t base = sb + st * STG16;
        int k0 = ch << 5;
#pragma unroll
        for (int j = 0; j < 4; j++) {
            int id = tid + j * 256;
            int t = id >> 9, w = id & 511;
            int row = w >> 2, c16 = (w & 3);
            cp16(base + t * TSZ + row * PITCHB + c16 * 16,
                 gp[t] + (long)row * K + k0 + c16 * 8);
        }
        asm volatile("cp.async.commit_group;" ::: "memory");
    };

    load_stage(0, 0);
    for (int i = 0; i < nch; i++) {
        int st = i & 1;
        if (i + 1 < nch) { load_stage(i + 1, st ^ 1);
            asm volatile("cp.async.wait_group 1;" ::: "memory");
        } else asm volatile("cp.async.wait_group 0;" ::: "memory");
        __syncthreads();
        uint32_t sA2 = sb + st * STG16, sB2 = sA2 + TSZ;
#pragma unroll
        for (int ks = 0; ks < 2; ks++) {
            uint32_t kb = (uint32_t)(ks * 16 + kadd) * 2;
            uint32_t bf[4][2];
#pragma unroll
            for (int p = 0; p < 2; p++) {
                uint32_t r[4];
                ldsm4(r, sB2 + (uint32_t)(rowB + p * 16) * PITCHB + kb);
                bf[p*2][0] = r[0]; bf[p*2][1] = r[2];
                bf[p*2+1][0] = r[1]; bf[p*2+1][1] = r[3];
            }
#pragma unroll
            for (int mt = 0; mt < 4; mt++) {
                uint32_t af[4];
                ldsm4(af, sA2 + (uint32_t)(rowA + mt * 16) * PITCHB + kb);
#pragma unroll
                for (int nt = 0; nt < 4; nt++) mmaf16(acc[mt][nt], af, bf[nt]);
            }
        }
        __syncthreads();
    }
    float* Cb = C + (long)blockIdx.z * sC;
#pragma unroll
    for (int mt = 0; mt < 4; mt++) {
        int m = m0 + wm * 64 + mt * 16 + (lane >> 2);
        float b0 = bias ? bias[m] : 0.f;
        float b1 = bias ? bias[m + 8] : 0.f;
#pragma unroll
        for (int nt = 0; nt < 4; nt++) {
            int n = n0 + wn * 32 + nt * 8 + (lane & 3) * 2;
            float2 v0 = { acc[mt][nt][0] + b0, acc[mt][nt][1] + b0 };
            float2 v1 = { acc[mt][nt][2] + b1, acc[mt][nt][3] + b1 };
            *(float2*)(Cb + (long)m * N + n) = v0;
            *(float2*)(Cb + (long)(m + 8) * N + n) = v1;
        }
    }
}

// ========= fp16 direct-conv GEMM (128x128 tile) =========
template<int LW, int CH, int PW, bool DIRECT>
__global__ __launch_bounds__(256) void tgemm_conv16(
    const __half* __restrict__ A, const __half* __restrict__ I,
    float* __restrict__ C, const float* __restrict__ bias, int N, int K)
{
    extern __shared__ __align__(128) char smem_raw[];
    const uint32_t sb = smem_u32(smem_raw);
    const int tid = threadIdx.x, wid = tid >> 5, lane = tid & 31;
    const int wm = wid >> 2, wn = wid & 3;
    const int m0 = blockIdx.y * 128, n0 = blockIdx.x * 128;
    const __half* pA = A + (long)m0 * K;
    constexpr int CPT = CH / 32;
    const int lg = lane >> 3, l8 = lane & 7;
    const int row_off = l8 + (lg & 1) * 8;
    const int kadd = (lg >> 1) * 8;
    const int rowA = wm * 64 + row_off;
    const int rowB = wn * 32 + row_off;

    float acc[4][4][4];
#pragma unroll
    for (int a = 0; a < 4; a++)
#pragma unroll
        for (int b = 0; b < 4; b++)
#pragma unroll
            for (int c = 0; c < 4; c++) acc[a][b][c] = 0.f;

    const int nch = K >> 5;
    auto load_stage = [&](int ch, int st) {
        uint32_t base = sb + st * STG16;
        int k0 = ch << 5;
        int tap = ch / CPT;
        int cc0 = (ch % CPT) << 5;
        int dyp = tap / 3, dxp = tap - dyp * 3;
#pragma unroll
        for (int j = 0; j < 4; j++) {
            int id = tid + j * 256;
            int t = id >> 9, w = id & 511;
            int row = w >> 2, c16 = (w & 3);
            uint32_t sa = base + t * TSZ + row * PITCHB + c16 * 16;
            if (t == 0) {
                cp16(sa, pA + (long)row * K + k0 + c16 * 8);
            } else {
                int n = n0 + row;
                int b = n >> (2 * LW);
                int pix = n & ((1 << (2 * LW)) - 1);
                int Y = pix >> LW, X = pix & ((1 << LW) - 1);
                long off = ((long)((b * PW + Y + dyp) * PW) + X + dxp) * CH + cc0 + c16 * 8;
                cp16(sa, I + off);
            }
        }
        asm volatile("cp.async.commit_group;" ::: "memory");
    };

    load_stage(0, 0);
    for (int i = 0; i < nch; i++) {
        int st = i & 1;
        if (i + 1 < nch) { load_stage(i + 1, st ^ 1);
            asm volatile("cp.async.wait_group 1;" ::: "memory");
        } else asm volatile("cp.async.wait_group 0;" ::: "memory");
        __syncthreads();
        uint32_t sA2 = sb + st * STG16, sB2 = sA2 + TSZ;
#pragma unroll
        for (int ks = 0; ks < 2; ks++) {
            uint32_t kb = (uint32_t)(ks * 16 + kadd) * 2;
            uint32_t bf[4][2];
#pragma unroll
            for (int p = 0; p < 2; p++) {
                uint32_t r[4];
                ldsm4(r, sB2 + (uint32_t)(rowB + p * 16) * PITCHB + kb);
                bf[p*2][0] = r[0]; bf[p*2][1] = r[2];
                bf[p*2+1][0] = r[1]; bf[p*2+1][1] = r[3];
            }
#pragma unroll
            for (int mt = 0; mt < 4; mt++) {
                uint32_t af[4];
                ldsm4(af, sA2 + (uint32_t)(rowA + mt * 16) * PITCHB + kb);
#pragma unroll
                for (int nt = 0; nt < 4; nt++) mmaf16(acc[mt][nt], af, bf[nt]);
            }
        }
        __syncthreads();
    }
#pragma unroll
    for (int mt = 0; mt < 4; mt++) {
        int m = m0 + wm * 64 + mt * 16 + (lane >> 2);
        float b0 = bias[m], b1 = bias[m + 8];
#pragma unroll
        for (int nt = 0; nt < 4; nt++) {
            int n = n0 + wn * 32 + nt * 8 + (lane & 3) * 2;
            float2 v0 = { acc[mt][nt][0] + b0, acc[mt][nt][1] + b0 };
            float2 v1 = { acc[mt][nt][2] + b1, acc[mt][nt][3] + b1 };
            if (DIRECT) {
                long base0 = ((long)(n >> 12) << 20) + (n & 4095);
                *(float2*)(C + base0 + (long)m * 4096) = v0;
                *(float2*)(C + base0 + (long)(m + 8) * 4096) = v1;
            } else {
                *(float2*)(C + (long)m * N + n) = v0;
                *(float2*)(C + (long)(m + 8) * N + n) = v1;
            }
        }
    }
}

// ========= fp16 PV GEMM =========
#define PVATSZ 2560
#define PVBTSZ 20480
#define PVSTG16 (PVATSZ + PVBTSZ)
#define PVSMEM16 (2*PVSTG16)
__global__ __launch_bounds__(256) void tgemm_pv16()
{
    extern __shared__ __align__(128) char smem_raw[];
    const uint32_t sb = smem_u32(smem_raw);
    const int tid = threadIdx.x, wid = tid >> 5, lane = tid & 31;
    const int n0 = blockIdx.x * 256;
    const int z = blockIdx.z;
    const __half* pA = g_vTp16 + (long)z * 32768;
    const __half* pB = g_Pp16 + (size_t)z * 1048576;
    const int lg = lane >> 3, l8 = lane & 7;
    const int row_off = l8 + (lg & 1) * 8;
    const int kadd = (lg >> 1) * 8;
    const int rowB = wid * 32 + row_off;

    float acc[2][4][4];
#pragma unroll
    for (int a = 0; a < 2; a++)
#pragma unroll
        for (int b = 0; b < 4; b++)
#pragma unroll
            for (int c = 0; c < 4; c++) acc[a][b][c] = 0.f;

    auto load_stage = [&](int ch, int st) {
        uint32_t base = sb + st * PVSTG16;
        int k0 = ch << 5;
#pragma unroll
        for (int j = 0; j < 5; j++) {
            int id = tid + j * 256;
            if (id < 128) {
                int row = id >> 2, c16 = id & 3;
                cp16(base + row * PITCHB + c16 * 16, pA + (long)row * 1024 + k0 + c16 * 8);
            } else if (id < 1152) {
                int w = id - 128;
                int row = w >> 2, c16 = w & 3;
                cp16(base + PVATSZ + row * PITCHB + c16 * 16,
                     pB + (long)(n0 + row) * 1024 + k0 + c16 * 8);
            }
        }
        asm volatile("cp.async.commit_group;" ::: "memory");
    };

    load_stage(0, 0);
    for (int i = 0; i < 32; i++) {
        int st = i & 1;
        if (i + 1 < 32) { load_stage(i + 1, st ^ 1);
            asm volatile("cp.async.wait_group 1;" ::: "memory");
        } else asm volatile("cp.async.wait_group 0;" ::: "memory");
        __syncthreads();
        uint32_t sA2 = sb + st * PVSTG16, sB2 = sA2 + PVATSZ;
#pragma unroll
        for (int ks = 0; ks < 2; ks++) {
            uint32_t kb = (uint32_t)(ks * 16 + kadd) * 2;
            uint32_t bf[4][2];
#pragma unroll
            for (int p = 0; p < 2; p++) {
                uint32_t r[4];
                ldsm4(r, sB2 + (uint32_t)(rowB + p * 16) * PITCHB + kb);
                bf[p*2][0] = r[0]; bf[p*2][1] = r[2];
                bf[p*2+1][0] = r[1]; bf[p*2+1][1] = r[3];
            }
#pragma unroll
            for (int mt = 0; mt < 2; mt++) {
                uint32_t af[4];
                ldsm4(af, sA2 + (uint32_t)(row_off + mt * 16) * PITCHB + kb);
#pragma unroll
                for (int nt = 0; nt < 4; nt++) mmaf16(acc[mt][nt], af, bf[nt]);
            }
        }
        __syncthreads();
    }
    float* Cb = g_PV + (long)z * 32768;
#pragma unroll
    for (int mt = 0; mt < 2; mt++) {
        int m = mt * 16 + (lane >> 2);
#pragma unroll
        for (int nt = 0; nt < 4; nt++) {
            int n = n0 + wid * 32 + nt * 8 + (lane & 3) * 2;
            *(float2*)(Cb + (long)m * 1024 + n) = *(float2*)&acc[mt][nt][0];
            *(float2*)(Cb + (long)(m + 8) * 1024 + n) = *(float2*)&acc[mt][nt][2];
        }
    }
}

// ---------------- reduce helpers ----------------
__device__ __forceinline__ float wmax(float v) {
#pragma unroll
    for (int o = 16; o; o >>= 1) v = fmaxf(v, __shfl_xor_sync(~0u, v, o));
    return v;
}
__device__ __forceinline__ float wsum(float v) {
#pragma unroll
    for (int o = 16; o; o >>= 1) v += __shfl_xor_sync(~0u, v, o);
    return v;
}

// ---------------- small kernels ----------------
__global__ void k_zero4(float4* p, int n4) {
    int i = blockIdx.x * 256 + threadIdx.x;
    if (i < n4) p[i] = make_float4(0.f, 0.f, 0.f, 0.f);
}
__global__ void k_wrd16(const float* __restrict__ W, __half* __restrict__ h, int CIN) {
    int idx = blockIdx.x * 256 + threadIdx.x;
    int K = CIN * 9;
    int oc = idx / K, rem = idx - oc * K;
    int cc = rem / 9, tap = rem - cc * 9;
    h[(long)oc * K + tap * CIN + cc] = __float2half(W[idx]);
}
__global__ void k_pack_w1(const float* __restrict__ Wq, const float* __restrict__ bq,
                          const float* __restrict__ Wk, const float* __restrict__ bk,
                          const float* __restrict__ Wv, const float* __restrict__ bv) {
    int idx = blockIdx.x * 256 + threadIdx.x;
    float v;
    if (idx < 65536) v = Wq[idx];
    else if (idx < 131072) v = Wk[idx - 65536];
    else v = Wv[idx - 131072];
    g_W116[idx] = __float2half(v);
    if (idx < 64) g_b1[idx] = bq[idx];
    else if (idx < 128) g_b1[idx] = bk[idx - 64];
    else if (idx < 384) g_b1[idx] = bv[idx - 128];
}
__global__ void k_im2col1(const float* __restrict__ x) {
    __shared__ float t[32][33];
    int k0 = blockIdx.x * 32, n0 = blockIdx.y * 32;
    int tx = threadIdx.x;
#pragma unroll
    for (int it = 0; it < 4; it++) {
        int ty = threadIdx.y + it * 8;
        int k = k0 + ty, n = n0 + tx;
        int c = k >> 2, ky = (k >> 1) & 1, kx = k & 1;
        int b = n >> 10, l = n & 1023, y = l >> 5, xq = l & 31;
        t[ty][tx] = x[(((b * 256 + c) * 64) + (y * 2 + ky)) * 64 + xq * 2 + kx];
    }
    __syncthreads();
#pragma unroll
    for (int it = 0; it < 4; it++) {
        int ty = threadIdx.y + it * 8;
        long o = (long)(n0 + ty) * 1024 + k0 + tx;
        g_X116[o] = __float2half(t[tx][ty]);
    }
}
__global__ void k_pos_attn() {
    __shared__ float Ks[8][1024];
    int b = blockIdx.z, h = blockIdx.y, tid = threadIdx.x;
    for (int idx = tid; idx < 8192; idx += 256) {
        int d = idx >> 10, k = idx & 1023;
        Ks[d][k] = g_P1[(64 + h * 8 + d) * BL + b * 1024 + k];
    }
    __syncthreads();
    int warp = tid >> 5, lane = tid & 31;
    int qb = blockIdx.x * 64 + warp * 8;
#pragma unroll 1
    for (int qq = 0; qq < 8; qq++) {
        int q = qb + qq;
        float Q[8];
#pragma unroll
        for (int d = 0; d < 8; d++) Q[d] = g_P1[(h * 8 + d) * BL + b * 1024 + q];
        float s[32], mx = -1e30f;
#pragma unroll
        for (int i = 0; i < 32; i++) {
            int k = i * 32 + lane;
            float sc = 0.f;
#pragma unroll
            for (int d = 0; d < 8; d++) sc += Q[d] * Ks[d][k];
            sc *= 0.35355339059327373f;
            s[i] = sc; mx = fmaxf(mx, sc);
        }
        mx = wmax(mx);
        float sum = 0.f;
#pragma unroll
        for (int i = 0; i < 32; i++) { float e = __expf(s[i] - mx); s[i] = e; sum += e; }
        float inv = 1.0f / wsum(sum);
        size_t ob = ((size_t)(b * 8 + h) * 1024 + q) * 1024 + lane;
#pragma unroll
        for (int i = 0; i < 32; i++) g_Pp16[ob + i * 32] = __float2half(s[i] * inv);
    }
}
__global__ void k_vtp() {
    int idx = blockIdx.x * 256 + threadIdx.x;
    int k = idx & 1023, d = (idx >> 10) & 31, bh = idx >> 15;
    g_vTp16[idx] = __float2half(g_P1[(128 + (bh & 7) * 32 + d) * BL + (bh >> 3) * 1024 + k]);
}
__global__ void k_o1t() {
    __shared__ float t[32][33];
    int q0 = blockIdx.x * 32, z = blockIdx.y;
    int b = z >> 3, h = z & 7;
    int tx = threadIdx.x;
#pragma unroll
    for (int it = 0; it < 4; it++) {
        int ty = threadIdx.y + it * 8;
        t[ty][tx] = g_PV[((long)z * 32 + ty) * 1024 + q0 + tx];
    }
    __syncthreads();
#pragma unroll
    for (int it = 0; it < 4; it++) {
        int ty = threadIdx.y + it * 8;
        int q = q0 + ty;
        int y = q >> 5, x = q & 31;
        long o = ((long)(b * 34 + 1 + y) * 34 + 1 + x) * 256 + h * 32 + tx;
        g_I216[o] = __float2half(t[tx][ty]);
    }
}
__global__ void k_cha_proj(const float* __restrict__ x,
                           const float* __restrict__ Wq, const float* __restrict__ bq,
                           const float* __restrict__ Wk, const float* __restrict__ bk,
                           const float* __restrict__ Wv, const float* __restrict__ bv) {
    int l = blockIdx.x * 256 + threadIdx.x;
    int g = blockIdx.y, b = blockIdx.z;
    int i = l >> 5, j = l & 31;
    const float* xp = x + ((b * 256 + g) * 64) * 64;
    float x00 = xp[2*i*64 + 2*j], x01 = xp[2*i*64 + 2*j + 1];
    float x10 = xp[(2*i+1)*64 + 2*j], x11 = xp[(2*i+1)*64 + 2*j + 1];
    int base = (b * 2048 + g * 8) * 1024 + l;
#pragma unroll
    for (int h = 0; h < 8; h++) {
        int w = (g * 8 + h) * 4, o = base + h * 1024;
        float qv = Wq[w]*x00 + Wq[w+1]*x01 + Wq[w+2]*x10 + Wq[w+3]*x11 + bq[g*8+h];
        float kv = Wk[w]*x00 + Wk[w+1]*x01 + Wk[w+2]*x10 + Wk[w+3]*x11 + bk[g*8+h];
        float vv = Wv[w]*x00 + Wv[w+1]*x01 + Wv[w+2]*x10 + Wv[w+3]*x11 + bv[g*8+h];
        g_qc16[o] = __float2half(qv);
        g_kc16[o] = __float2half(kv);
        g_vc[o] = vv;
    }
}
__global__ void k_vcT() {
    __shared__ float t[32][33];
    int z = blockIdx.z, c0 = blockIdx.x * 32, l0 = blockIdx.y * 32;
    int tx = threadIdx.x;
    const float* src = g_vc + (long)z * 262144;
#pragma unroll
    for (int it = 0; it < 4; it++) {
        int ty = threadIdx.y + it * 8;
        t[ty][tx] = src[(c0 + ty) * 1024 + l0 + tx];
    }
    __syncthreads();
#pragma unroll
    for (int it = 0; it < 4; it++) {
        int ty = threadIdx.y + it * 8;
        long o = (long)z * 262144 + (long)(l0 + ty) * 256 + c0 + tx;
        g_vT16[o] = __float2half(t[tx][ty]);
    }
}
__global__ void k_cha_softmax() {
    int row = blockIdx.x * 8 + (threadIdx.x >> 5);
    int lane = threadIdx.x & 31;
    const float* r = g_Sc + (long)row * 256;
    float v[8], mx = -1e30f;
#pragma unroll
    for (int j = 0; j < 8; j++) { v[j] = r[j * 32 + lane] * 0.03125f; mx = fmaxf(mx, v[j]); }
    mx = wmax(mx);
    float sum = 0.f;
#pragma unroll
    for (int j = 0; j < 8; j++) { v[j] = __expf(v[j] - mx); sum += v[j]; }
    float inv = 1.0f / wsum(sum);
#pragma unroll
    for (int j = 0; j < 8; j++)
        g_Pc16[(long)row * 256 + j * 32 + lane] = __float2half(v[j] * inv);
}
__global__ void k_fusepack(const float* __restrict__ xp_, const float* __restrict__ xc_,
                           const float* __restrict__ Wt, const float* __restrict__ bt,
                           const float* __restrict__ gp_, const float* __restrict__ gc_) {
    __shared__ float t[32][33];
    int c0 = blockIdx.x * 32, p0 = blockIdx.y * 32, b = blockIdx.z;
    int tx = threadIdx.x;
    float gp = gp_[0], gc = gc_[0];
#pragma unroll
    for (int it = 0; it < 4; it++) {
        int ty = threadIdx.y + it * 8;
        int c = c0 + ty, pix = p0 + tx;
        int Y = pix >> 6, X = pix & 63;
        float v;
        if (c < 256) {
            float sy = Y * 0.5f - 0.25f, sx = X * 0.5f - 0.25f;
            int y0 = (int)floorf(sy); float fy = sy - y0;
            int x0 = (int)floorf(sx); float fx = sx - x0;
            int y1 = min(y0 + 1, 31); y0 = max(y0, 0);
            int x1 = min(x0 + 1, 31); x0 = max(x0, 0);
            const float* p = g_O2 + c * 8192 + b * 1024;
            float u = (1.f - fy) * ((1.f - fx) * p[y0*32+x0] + fx * p[y0*32+x1])
                    + fy * ((1.f - fx) * p[y1*32+x0] + fx * p[y1*32+x1]);
            v = xp_[((b * 256 + c) * 4096) + pix] + gp * u;
        } else {
            int g = c - 256;
            int pp = Y >> 1, ky = Y & 1, qq = X >> 1, kx = X & 1;
            float s = bt[g];
            int ob = (b * 2048 + g * 8) * 1024 + pp * 32 + qq;
#pragma unroll
            for (int i = 0; i < 8; i++)
                s += g_oc[ob + i * 1024] * Wt[(g * 8 + i) * 4 + ky * 2 + kx];
            v = xc_[((b * 256 + g) * 4096) + pix] + gc * s;
        }
        t[ty][tx] = v;
    }
    __syncthreads();
#pragma unroll
    for (int it = 0; it < 4; it++) {
        int ty = threadIdx.y + it * 8;
        int pix = p0 + ty, c = c0 + tx;
        int Y = pix >> 6, X = pix & 63;
        long o = ((long)(b * 66 + 1 + Y) * 66 + 1 + X) * 512 + c;
        g_I316[o] = __float2half(t[tx][ty]);
    }
}

// ---------------- launch ----------------
static void* sym(const void* s) { void* p = nullptr; cudaGetSymbolAddress(&p, s); return p; }

extern "C" void kernel_launch(void* const* d_in, const int* in_sizes, int n_in,
                              void* d_out, int out_size) {
    const float *qkv_pos = (const float*)d_in[0], *qkv_cha = (const float*)d_in[1];
    const float *Wq_pos = (const float*)d_in[2], *bq_pos = (const float*)d_in[3];
    const float *Wk_pos = (const float*)d_in[4], *bk_pos = (const float*)d_in[5];
    const float *Wv_pos = (const float*)d_in[6], *bv_pos = (const float*)d_in[7];
    const float *Wo_pos = (const float*)d_in[8], *bo_pos = (const float*)d_in[9];
    const float *gamma_pos = (const float*)d_in[10];
    const float *Wq_cha = (const float*)d_in[11], *bq_cha = (const float*)d_in[12];
    const float *Wk_cha = (const float*)d_in[13], *bk_cha = (const float*)d_in[14];
    const float *Wv_cha = (const float*)d_in[15], *bv_cha = (const float*)d_in[16];
    const float *Wt_cha = (const float*)d_in[17], *bt_cha = (const float*)d_in[18];
    const float *gamma_cha = (const float*)d_in[19];
    const float *Wf = (const float*)d_in[20], *bf = (const float*)d_in[21];
    float* out = (float*)d_out;

    static cudaStream_t s1 = nullptr;
    static cudaEvent_t evF = nullptr, evJ = nullptr;
    if (!s1) {
        cudaStreamCreateWithFlags(&s1, cudaStreamNonBlocking);
        cudaEventCreateWithFlags(&evF, cudaEventDisableTiming);
        cudaEventCreateWithFlags(&evJ, cudaEventDisableTiming);
        cudaFuncSetAttribute(tgemm16, cudaFuncAttributeMaxDynamicSharedMemorySize, TSMEM16);
        cudaFuncSetAttribute(tgemm_conv16<5,256,34,false>, cudaFuncAttributeMaxDynamicSharedMemorySize, TSMEM16);
        cudaFuncSetAttribute(tgemm_conv16<6,512,66,true>, cudaFuncAttributeMaxDynamicSharedMemorySize, TSMEM16);
        cudaFuncSetAttribute(tgemm_pv16, cudaFuncAttributeMaxDynamicSharedMemorySize, PVSMEM16);
    }

    __half *pW116 = (__half*)sym(g_W116), *pX116 = (__half*)sym(g_X116);
    __half *pWo16 = (__half*)sym(g_Wo16), *pI216 = (__half*)sym(g_I216);
    __half *pWf16 = (__half*)sym(g_Wf16), *pI316 = (__half*)sym(g_I316);
    __half *pqc16 = (__half*)sym(g_qc16), *pkc16 = (__half*)sym(g_kc16);
    __half *pvT16 = (__half*)sym(g_vT16), *pPc16 = (__half*)sym(g_Pc16);
    float *pb1 = (float*)sym(g_b1), *pP1 = (float*)sym(g_P1);
    float *pO2 = (float*)sym(g_O2), *pSc = (float*)sym(g_Sc), *poc = (float*)sym(g_oc);

    // ---- fork: CHA branch + fusion prep on s1 ----
    cudaEventRecord(evF, 0);
    cudaStreamWaitEvent(s1, evF, 0);

    k_zero4<<<4356, 256, 0, s1>>>((float4*)pI316, 1115136);
    k_wrd16<<<4608, 256, 0, s1>>>(Wf, pWf16, 512);
    k_cha_proj<<<dim3(4, 256, 8), 256, 0, s1>>>(qkv_cha, Wq_cha, bq_cha, Wk_cha, bk_cha, Wv_cha, bv_cha);
    k_vcT<<<dim3(8, 32, 64), dim3(32, 8), 0, s1>>>();
    tgemm16<<<dim3(2, 2, 64), 256, TSMEM16, s1>>>(pqc16, pkc16, pSc, nullptr, 256, 1024, 262144L, 262144L, 65536L);
    k_cha_softmax<<<2048, 256, 0, s1>>>();
    tgemm16<<<dim3(8, 2, 64), 256, TSMEM16, s1>>>(pPc16, pvT16, poc, nullptr, 1024, 256, 65536L, 262144L, 262144L);
    cudaEventRecord(evJ, s1);

    // ---- POS branch on default stream ----
    k_pack_w1<<<1536, 256>>>(Wq_pos, bq_pos, Wk_pos, bk_pos, Wv_pos, bv_pos);
    k_im2col1<<<dim3(32, 256), dim3(32, 8)>>>(qkv_pos);
    k_zero4<<<578, 256>>>((float4*)pI216, 147968);
    tgemm16<<<dim3(64, 3, 1), 256, TSMEM16>>>(pW116, pX116, pP1, pb1, 8192, 1024, 0, 0, 0);
    k_pos_attn<<<dim3(16, 8, 8), 256>>>();
    k_vtp<<<8192, 256>>>();
    tgemm_pv16<<<dim3(4, 1, 64), 256, PVSMEM16>>>();
    k_o1t<<<dim3(32, 64), dim3(32, 8)>>>();
    k_wrd16<<<2304, 256>>>(Wo_pos, pWo16, 256);
    tgemm_conv16<5,256,34,false><<<dim3(64, 2), 256, TSMEM16>>>(pWo16, pI216, pO2, bo_pos, 8192, 2304);

    // ---- join + fused residual/pack + fusion conv direct to out ----
    cudaStreamWaitEvent(0, evJ, 0);
    k_fusepack<<<dim3(16, 128, 8), dim3(32, 8)>>>(qkv_pos, qkv_cha, Wt_cha, bt_cha, gamma_pos, gamma_cha);
    tgemm_conv16<6,512,66,true><<<dim3(256, 2), 256, TSMEM16>>>(pWf16, pI316, out, bf, 32768, 4608);
}

// round 14
// speedup vs baseline: 1.1106x; 1.0149x over previous
#include <cuda_runtime.h>
#include <cuda_fp16.h>
#include <math.h>
#include <stdint.h>

#define Bz 8
#define BL 8192

__device__ __forceinline__ uint32_t smem_u32(const void* p) {
    uint32_t a;
    asm("{ .reg .u64 t; cvta.to.shared.u64 t, %1; cvt.u32.u64 %0, t; }" : "=r"(a) : "l"(p));
    return a;
}
__device__ __forceinline__ void cp16(uint32_t s, const void* g) {
    unsigned long long ga = (unsigned long long)__cvta_generic_to_global(g);
    asm volatile("cp.async.cg.shared.global [%0], [%1], 16;" :: "r"(s), "l"(ga));
}
__device__ __forceinline__ void ldsm4(uint32_t* r, uint32_t a) {
    asm volatile("ldmatrix.sync.aligned.m8n8.x4.shared.b16 {%0,%1,%2,%3}, [%4];"
                 : "=r"(r[0]), "=r"(r[1]), "=r"(r[2]), "=r"(r[3]) : "r"(a));
}
__device__ __forceinline__ void mmaf16(float* c, const uint32_t* a, const uint32_t* b) {
    asm volatile("mma.sync.aligned.m16n8k16.row.col.f32.f16.f16.f32 "
                 "{%0,%1,%2,%3}, {%4,%5,%6,%7}, {%8,%9}, {%0,%1,%2,%3};"
                 : "+f"(c[0]), "+f"(c[1]), "+f"(c[2]), "+f"(c[3])
                 : "r"(a[0]), "r"(a[1]), "r"(a[2]), "r"(a[3]), "r"(b[0]), "r"(b[1]));
}
__device__ __forceinline__ void stpair(float* C, long idx, float v0, float v1) {
    *(float2*)(C + idx) = make_float2(v0, v1);
}
__device__ __forceinline__ void stpair(__half* C, long idx, float v0, float v1) {
    *(__half2*)(C + idx) = __floats2half2_rn(v0, v1);
}

// ---------------- scratch ----------------
#define AL __align__(256)
__device__ AL __half g_W116[384*1024];
__device__ float g_b1[384];
__device__ AL __half g_X116[8192*1024];
__device__ AL __half g_P116[384*8192];
__device__ AL __half g_Pp16[(size_t)64*1024*1024];
__device__ AL __half g_vTp16[64*32*1024];
__device__ AL __half g_PV16[64*32*1024];
__device__ AL __half g_Wo16[256*2304];
__device__ AL __half g_I216[8*34*34*256];
__device__ AL __half g_O216[256*8192];
__device__ AL __half g_qc16[8*2048*1024], g_kc16[8*2048*1024];
__device__ AL __half g_vc16[8*2048*1024];
__device__ AL __half g_vT16[64*1024*256];
__device__ AL __half g_Sc16[64*256*256];
__device__ AL __half g_Pc16[64*256*256];
__device__ AL __half g_oc16[8*2048*1024];
__device__ AL __half g_Wf16[256*4608];
__device__ AL __half g_I316[8*66*66*512];

#define PITCHB 80
#define TSZ 10240

// ========= fp16 single-term GEMM (128x128 tile, 8 warps, 2-stage) =========
// TO: output type. VOUT: proj mode — rows m>=128 (V) go to g_vTp16 [bh][d][k].
#define STG16 20480
#define TSMEM16 (2*STG16)
template<typename TO, bool VOUT>
__global__ __launch_bounds__(256) void tgemm16(
    const __half* __restrict__ A, const __half* __restrict__ B,
    TO* __restrict__ C, const float* __restrict__ bias,
    int N, int K, long sA, long sB, long sC)
{
    extern __shared__ __align__(128) char smem_raw[];
    const uint32_t sb = smem_u32(smem_raw);
    const int tid = threadIdx.x, wid = tid >> 5, lane = tid & 31;
    const int wm = wid >> 2, wn = wid & 3;
    const int m0 = blockIdx.y * 128, n0 = blockIdx.x * 128;
    const __half* gp[2] = { A + (long)blockIdx.z * sA + (long)m0 * K,
                            B + (long)blockIdx.z * sB + (long)n0 * K };
    const int lg = lane >> 3, l8 = lane & 7;
    const int row_off = l8 + (lg & 1) * 8;
    const int kadd = (lg >> 1) * 8;
    const int rowA = wm * 64 + row_off;
    const int rowB = wn * 32 + row_off;

    float acc[4][4][4];
#pragma unroll
    for (int a = 0; a < 4; a++)
#pragma unroll
        for (int b = 0; b < 4; b++)
#pragma unroll
            for (int c = 0; c < 4; c++) acc[a][b][c] = 0.f;

    const int nch = K >> 5;
    auto load_stage = [&](int ch, int st) {
        uint32_t base = sb + st * STG16;
        int k0 = ch << 5;
#pragma unroll
        for (int j = 0; j < 4; j++) {
            int id = tid + j * 256;
            int t = id >> 9, w = id & 511;
            int row = w >> 2, c16 = (w & 3);
            cp16(base + t * TSZ + row * PITCHB + c16 * 16,
                 gp[t] + (long)row * K + k0 + c16 * 8);
        }
        asm volatile("cp.async.commit_group;" ::: "memory");
    };

    load_stage(0, 0);
    for (int i = 0; i < nch; i++) {
        int st = i & 1;
        if (i + 1 < nch) { load_stage(i + 1, st ^ 1);
            asm volatile("cp.async.wait_group 1;" ::: "memory");
        } else asm volatile("cp.async.wait_group 0;" ::: "memory");
        __syncthreads();
        uint32_t sA2 = sb + st * STG16, sB2 = sA2 + TSZ;
#pragma unroll
        for (int ks = 0; ks < 2; ks++) {
            uint32_t kb = (uint32_t)(ks * 16 + kadd) * 2;
            uint32_t bf[4][2];
#pragma unroll
            for (int p = 0; p < 2; p++) {
                uint32_t r[4];
                ldsm4(r, sB2 + (uint32_t)(rowB + p * 16) * PITCHB + kb);
                bf[p*2][0] = r[0]; bf[p*2][1] = r[2];
                bf[p*2+1][0] = r[1]; bf[p*2+1][1] = r[3];
            }
#pragma unroll
            for (int mt = 0; mt < 4; mt++) {
                uint32_t af[4];
                ldsm4(af, sA2 + (uint32_t)(rowA + mt * 16) * PITCHB + kb);
#pragma unroll
                for (int nt = 0; nt < 4; nt++) mmaf16(acc[mt][nt], af, bf[nt]);
            }
        }
        __syncthreads();
    }
    TO* Cb = C + (long)blockIdx.z * sC;
#pragma unroll
    for (int mt = 0; mt < 4; mt++) {
        int m = m0 + wm * 64 + mt * 16 + (lane >> 2);
        float b0 = bias ? bias[m] : 0.f;
        float b1 = bias ? bias[m + 8] : 0.f;
#pragma unroll
        for (int nt = 0; nt < 4; nt++) {
            int n = n0 + wn * 32 + nt * 8 + (lane & 3) * 2;
            float v0 = acc[mt][nt][0] + b0, v1 = acc[mt][nt][1] + b0;
            float v2 = acc[mt][nt][2] + b1, v3 = acc[mt][nt][3] + b1;
            if (VOUT && m >= 128) {
                // V rows -> g_vTp16 [bh][d][k]; n = b*1024 + k
                int kk = n & 1023, bb = n >> 10;
                int z1 = bb * 8 + ((m - 128) >> 5), d1 = (m - 128) & 31;
                int z2 = bb * 8 + ((m - 120) >> 5), d2 = (m - 120) & 31;
                *(__half2*)(g_vTp16 + ((long)z1 * 32 + d1) * 1024 + kk) = __floats2half2_rn(v0, v1);
                *(__half2*)(g_vTp16 + ((long)z2 * 32 + d2) * 1024 + kk) = __floats2half2_rn(v2, v3);
            } else {
                stpair(Cb, (long)m * N + n, v0, v1);
                stpair(Cb, (long)(m + 8) * N + n, v2, v3);
            }
        }
    }
}

// ========= fp16 direct-conv GEMM (128x128 tile) =========
template<int LW, int CH, int PW, bool DIRECT, typename TO>
__global__ __launch_bounds__(256) void tgemm_conv16(
    const __half* __restrict__ A, const __half* __restrict__ I,
    TO* __restrict__ C, const float* __restrict__ bias, int N, int K)
{
    extern __shared__ __align__(128) char smem_raw[];
    const uint32_t sb = smem_u32(smem_raw);
    const int tid = threadIdx.x, wid = tid >> 5, lane = tid & 31;
    const int wm = wid >> 2, wn = wid & 3;
    const int m0 = blockIdx.y * 128, n0 = blockIdx.x * 128;
    const __half* pA = A + (long)m0 * K;
    constexpr int CPT = CH / 32;
    const int lg = lane >> 3, l8 = lane & 7;
    const int row_off = l8 + (lg & 1) * 8;
    const int kadd = (lg >> 1) * 8;
    const int rowA = wm * 64 + row_off;
    const int rowB = wn * 32 + row_off;

    float acc[4][4][4];
#pragma unroll
    for (int a = 0; a < 4; a++)
#pragma unroll
        for (int b = 0; b < 4; b++)
#pragma unroll
            for (int c = 0; c < 4; c++) acc[a][b][c] = 0.f;

    const int nch = K >> 5;
    auto load_stage = [&](int ch, int st) {
        uint32_t base = sb + st * STG16;
        int k0 = ch << 5;
        int tap = ch / CPT;
        int cc0 = (ch % CPT) << 5;
        int dyp = tap / 3, dxp = tap - dyp * 3;
#pragma unroll
        for (int j = 0; j < 4; j++) {
            int id = tid + j * 256;
            int t = id >> 9, w = id & 511;
            int row = w >> 2, c16 = (w & 3);
            uint32_t sa = base + t * TSZ + row * PITCHB + c16 * 16;
            if (t == 0) {
                cp16(sa, pA + (long)row * K + k0 + c16 * 8);
            } else {
                int n = n0 + row;
                int b = n >> (2 * LW);
                int pix = n & ((1 << (2 * LW)) - 1);
                int Y = pix >> LW, X = pix & ((1 << LW) - 1);
                long off = ((long)((b * PW + Y + dyp) * PW) + X + dxp) * CH + cc0 + c16 * 8;
                cp16(sa, I + off);
            }
        }
        asm volatile("cp.async.commit_group;" ::: "memory");
    };

    load_stage(0, 0);
    for (int i = 0; i < nch; i++) {
        int st = i & 1;
        if (i + 1 < nch) { load_stage(i + 1, st ^ 1);
            asm volatile("cp.async.wait_group 1;" ::: "memory");
        } else asm volatile("cp.async.wait_group 0;" ::: "memory");
        __syncthreads();
        uint32_t sA2 = sb + st * STG16, sB2 = sA2 + TSZ;
#pragma unroll
        for (int ks = 0; ks < 2; ks++) {
            uint32_t kb = (uint32_t)(ks * 16 + kadd) * 2;
            uint32_t bf[4][2];
#pragma unroll
            for (int p = 0; p < 2; p++) {
                uint32_t r[4];
                ldsm4(r, sB2 + (uint32_t)(rowB + p * 16) * PITCHB + kb);
                bf[p*2][0] = r[0]; bf[p*2][1] = r[2];
                bf[p*2+1][0] = r[1]; bf[p*2+1][1] = r[3];
            }
#pragma unroll
            for (int mt = 0; mt < 4; mt++) {
                uint32_t af[4];
                ldsm4(af, sA2 + (uint32_t)(rowA + mt * 16) * PITCHB + kb);
#pragma unroll
                for (int nt = 0; nt < 4; nt++) mmaf16(acc[mt][nt], af, bf[nt]);
            }
        }
        __syncthreads();
    }
#pragma unroll
    for (int mt = 0; mt < 4; mt++) {
        int m = m0 + wm * 64 + mt * 16 + (lane >> 2);
        float b0 = bias[m], b1 = bias[m + 8];
#pragma unroll
        for (int nt = 0; nt < 4; nt++) {
            int n = n0 + wn * 32 + nt * 8 + (lane & 3) * 2;
            float v0 = acc[mt][nt][0] + b0, v1 = acc[mt][nt][1] + b0;
            float v2 = acc[mt][nt][2] + b1, v3 = acc[mt][nt][3] + b1;
            if (DIRECT) {
                long base0 = ((long)(n >> 12) << 20) + (n & 4095);
                stpair(C, base0 + (long)m * 4096, v0, v1);
                stpair(C, base0 + (long)(m + 8) * 4096, v2, v3);
            } else {
                stpair(C, (long)m * N + n, v0, v1);
                stpair(C, (long)(m + 8) * N + n, v2, v3);
            }
        }
    }
}

// ========= fp16 PV GEMM =========
#define PVATSZ 2560
#define PVBTSZ 20480
#define PVSTG16 (PVATSZ + PVBTSZ)
#define PVSMEM16 (2*PVSTG16)
__global__ __launch_bounds__(256) void tgemm_pv16()
{
    extern __shared__ __align__(128) char smem_raw[];
    const uint32_t sb = smem_u32(smem_raw);
    const int tid = threadIdx.x, wid = tid >> 5, lane = tid & 31;
    const int n0 = blockIdx.x * 256;
    const int z = blockIdx.z;
    const __half* pA = g_vTp16 + (long)z * 32768;
    const __half* pB = g_Pp16 + (size_t)z * 1048576;
    const int lg = lane >> 3, l8 = lane & 7;
    const int row_off = l8 + (lg & 1) * 8;
    const int kadd = (lg >> 1) * 8;
    const int rowB = wid * 32 + row_off;

    float acc[2][4][4];
#pragma unroll
    for (int a = 0; a < 2; a++)
#pragma unroll
        for (int b = 0; b < 4; b++)
#pragma unroll
            for (int c = 0; c < 4; c++) acc[a][b][c] = 0.f;

    auto load_stage = [&](int ch, int st) {
        uint32_t base = sb + st * PVSTG16;
        int k0 = ch << 5;
#pragma unroll
        for (int j = 0; j < 5; j++) {
            int id = tid + j * 256;
            if (id < 128) {
                int row = id >> 2, c16 = id & 3;
                cp16(base + row * PITCHB + c16 * 16, pA + (long)row * 1024 + k0 + c16 * 8);
            } else if (id < 1152) {
                int w = id - 128;
                int row = w >> 2, c16 = w & 3;
                cp16(base + PVATSZ + row * PITCHB + c16 * 16,
                     pB + (long)(n0 + row) * 1024 + k0 + c16 * 8);
            }
        }
        asm volatile("cp.async.commit_group;" ::: "memory");
    };

    load_stage(0, 0);
    for (int i = 0; i < 32; i++) {
        int st = i & 1;
        if (i + 1 < 32) { load_stage(i + 1, st ^ 1);
            asm volatile("cp.async.wait_group 1;" ::: "memory");
        } else asm volatile("cp.async.wait_group 0;" ::: "memory");
        __syncthreads();
        uint32_t sA2 = sb + st * PVSTG16, sB2 = sA2 + PVATSZ;
#pragma unroll
        for (int ks = 0; ks < 2; ks++) {
            uint32_t kb = (uint32_t)(ks * 16 + kadd) * 2;
            uint32_t bf[4][2];
#pragma unroll
            for (int p = 0; p < 2; p++) {
                uint32_t r[4];
                ldsm4(r, sB2 + (uint32_t)(rowB + p * 16) * PITCHB + kb);
                bf[p*2][0] = r[0]; bf[p*2][1] = r[2];
                bf[p*2+1][0] = r[1]; bf[p*2+1][1] = r[3];
            }
#pragma unroll
            for (int mt = 0; mt < 2; mt++) {
                uint32_t af[4];
                ldsm4(af, sA2 + (uint32_t)(row_off + mt * 16) * PITCHB + kb);
#pragma unroll
                for (int nt = 0; nt < 4; nt++) mmaf16(acc[mt][nt], af, bf[nt]);
            }
        }
        __syncthreads();
    }
    __half* Cb = g_PV16 + (long)z * 32768;
#pragma unroll
    for (int mt = 0; mt < 2; mt++) {
        int m = mt * 16 + (lane >> 2);
#pragma unroll
        for (int nt = 0; nt < 4; nt++) {
            int n = n0 + wid * 32 + nt * 8 + (lane & 3) * 2;
            stpair(Cb, (long)m * 1024 + n, acc[mt][nt][0], acc[mt][nt][1]);
            stpair(Cb, (long)(m + 8) * 1024 + n, acc[mt][nt][2], acc[mt][nt][3]);
        }
    }
}

// ---------------- reduce helpers ----------------
__device__ __forceinline__ float wmax(float v) {
#pragma unroll
    for (int o = 16; o; o >>= 1) v = fmaxf(v, __shfl_xor_sync(~0u, v, o));
    return v;
}
__device__ __forceinline__ float wsum(float v) {
#pragma unroll
    for (int o = 16; o; o >>= 1) v += __shfl_xor_sync(~0u, v, o);
    return v;
}

// ---------------- small kernels ----------------
__global__ void k_zero4(float4* p, int n4) {
    int i = blockIdx.x * 256 + threadIdx.x;
    if (i < n4) p[i] = make_float4(0.f, 0.f, 0.f, 0.f);
}
__global__ void k_wrd16(const float* __restrict__ W, __half* __restrict__ h, int CIN) {
    int idx = blockIdx.x * 256 + threadIdx.x;
    int K = CIN * 9;
    int oc = idx / K, rem = idx - oc * K;
    int cc = rem / 9, tap = rem - cc * 9;
    h[(long)oc * K + tap * CIN + cc] = __float2half(W[idx]);
}
__global__ void k_pack_w1(const float* __restrict__ Wq, const float* __restrict__ bq,
                          const float* __restrict__ Wk, const float* __restrict__ bk,
                          const float* __restrict__ Wv, const float* __restrict__ bv) {
    int idx = blockIdx.x * 256 + threadIdx.x;
    float v;
    if (idx < 65536) v = Wq[idx];
    else if (idx < 131072) v = Wk[idx - 65536];
    else v = Wv[idx - 131072];
    g_W116[idx] = __float2half(v);
    if (idx < 64) g_b1[idx] = bq[idx];
    else if (idx < 128) g_b1[idx] = bk[idx - 64];
    else if (idx < 384) g_b1[idx] = bv[idx - 128];
}
__global__ void k_im2col1(const float* __restrict__ x) {
    __shared__ float t[32][33];
    int k0 = blockIdx.x * 32, n0 = blockIdx.y * 32;
    int tx = threadIdx.x;
#pragma unroll
    for (int it = 0; it < 4; it++) {
        int ty = threadIdx.y + it * 8;
        int k = k0 + ty, n = n0 + tx;
        int c = k >> 2, ky = (k >> 1) & 1, kx = k & 1;
        int b = n >> 10, l = n & 1023, y = l >> 5, xq = l & 31;
        t[ty][tx] = x[(((b * 256 + c) * 64) + (y * 2 + ky)) * 64 + xq * 2 + kx];
    }
    __syncthreads();
#pragma unroll
    for (int it = 0; it < 4; it++) {
        int ty = threadIdx.y + it * 8;
        long o = (long)(n0 + ty) * 1024 + k0 + tx;
        g_X116[o] = __float2half(t[tx][ty]);
    }
}
__global__ void k_pos_attn() {
    __shared__ float Ks[8][1024];
    int b = blockIdx.z, h = blockIdx.y, tid = threadIdx.x;
    for (int idx = tid; idx < 8192; idx += 256) {
        int d = idx >> 10, k = idx & 1023;
        Ks[d][k] = __half2float(g_P116[(long)(64 + h * 8 + d) * BL + b * 1024 + k]);
    }
    __syncthreads();
    int warp = tid >> 5, lane = tid & 31;
    int qb = blockIdx.x * 64 + warp * 8;
#pragma unroll 1
    for (int qq = 0; qq < 8; qq++) {
        int q = qb + qq;
        float Q[8];
#pragma unroll
        for (int d = 0; d < 8; d++)
            Q[d] = __half2float(g_P116[(long)(h * 8 + d) * BL + b * 1024 + q]);
        float s[32], mx = -1e30f;
#pragma unroll
        for (int i = 0; i < 32; i++) {
            int k = i * 32 + lane;
            float sc = 0.f;
#pragma unroll
            for (int d = 0; d < 8; d++) sc += Q[d] * Ks[d][k];
            sc *= 0.35355339059327373f;
            s[i] = sc; mx = fmaxf(mx, sc);
        }
        mx = wmax(mx);
        float sum = 0.f;
#pragma unroll
        for (int i = 0; i < 32; i++) { float e = __expf(s[i] - mx); s[i] = e; sum += e; }
        float inv = 1.0f / wsum(sum);
        size_t ob = ((size_t)(b * 8 + h) * 1024 + q) * 1024 + lane;
#pragma unroll
        for (int i = 0; i < 32; i++) g_Pp16[ob + i * 32] = __float2half(s[i] * inv);
    }
}
__global__ void k_o1t() {
    __shared__ float t[32][33];
    int q0 = blockIdx.x * 32, z = blockIdx.y;
    int b = z >> 3, h = z & 7;
    int tx = threadIdx.x;
#pragma unroll
    for (int it = 0; it < 4; it++) {
        int ty = threadIdx.y + it * 8;
        t[ty][tx] = __half2float(g_PV16[((long)z * 32 + ty) * 1024 + q0 + tx]);
    }
    __syncthreads();
#pragma unroll
    for (int it = 0; it < 4; it++) {
        int ty = threadIdx.y + it * 8;
        int q = q0 + ty;
        int y = q >> 5, x = q & 31;
        long o = ((long)(b * 34 + 1 + y) * 34 + 1 + x) * 256 + h * 32 + tx;
        g_I216[o] = __float2half(t[tx][ty]);
    }
}
__global__ void k_cha_proj(const float* __restrict__ x,
                           const float* __restrict__ Wq, const float* __restrict__ bq,
                           const float* __restrict__ Wk, const float* __restrict__ bk,
                           const float* __restrict__ Wv, const float* __restrict__ bv) {
    int l = blockIdx.x * 256 + threadIdx.x;
    int g = blockIdx.y, b = blockIdx.z;
    int i = l >> 5, j = l & 31;
    const float* xp = x + ((b * 256 + g) * 64) * 64;
    float x00 = xp[2*i*64 + 2*j], x01 = xp[2*i*64 + 2*j + 1];
    float x10 = xp[(2*i+1)*64 + 2*j], x11 = xp[(2*i+1)*64 + 2*j + 1];
    int base = (b * 2048 + g * 8) * 1024 + l;
#pragma unroll
    for (int h = 0; h < 8; h++) {
        int w = (g * 8 + h) * 4, o = base + h * 1024;
        float qv = Wq[w]*x00 + Wq[w+1]*x01 + Wq[w+2]*x10 + Wq[w+3]*x11 + bq[g*8+h];
        float kv = Wk[w]*x00 + Wk[w+1]*x01 + Wk[w+2]*x10 + Wk[w+3]*x11 + bk[g*8+h];
        float vv = Wv[w]*x00 + Wv[w+1]*x01 + Wv[w+2]*x10 + Wv[w+3]*x11 + bv[g*8+h];
        g_qc16[o] = __float2half(qv);
        g_kc16[o] = __float2half(kv);
        g_vc16[o] = __float2half(vv);
    }
}
__global__ void k_vcT() {
    __shared__ float t[32][33];
    int z = blockIdx.z, c0 = blockIdx.x * 32, l0 = blockIdx.y * 32;
    int tx = threadIdx.x;
    const __half* src = g_vc16 + (long)z * 262144;
#pragma unroll
    for (int it = 0; it < 4; it++) {
        int ty = threadIdx.y + it * 8;
        t[ty][tx] = __half2float(src[(c0 + ty) * 1024 + l0 + tx]);
    }
    __syncthreads();
#pragma unroll
    for (int it = 0; it < 4; it++) {
        int ty = threadIdx.y + it * 8;
        long o = (long)z * 262144 + (long)(l0 + ty) * 256 + c0 + tx;
        g_vT16[o] = __float2half(t[tx][ty]);
    }
}
__global__ void k_cha_softmax() {
    int row = blockIdx.x * 8 + (threadIdx.x >> 5);
    int lane = threadIdx.x & 31;
    const __half* r = g_Sc16 + (long)row * 256;
    float v[8], mx = -1e30f;
#pragma unroll
    for (int j = 0; j < 8; j++) {
        v[j] = __half2float(r[j * 32 + lane]) * 0.03125f;
        mx = fmaxf(mx, v[j]);
    }
    mx = wmax(mx);
    float sum = 0.f;
#pragma unroll
    for (int j = 0; j < 8; j++) { v[j] = __expf(v[j] - mx); sum += v[j]; }
    float inv = 1.0f / wsum(sum);
#pragma unroll
    for (int j = 0; j < 8; j++)
        g_Pc16[(long)row * 256 + j * 32 + lane] = __float2half(v[j] * inv);
}
__global__ void k_fusepack(const float* __restrict__ xp_, const float* __restrict__ xc_,
                           const float* __restrict__ Wt, const float* __restrict__ bt,
                           const float* __restrict__ gp_, const float* __restrict__ gc_) {
    __shared__ float t[32][33];
    int c0 = blockIdx.x * 32, p0 = blockIdx.y * 32, b = blockIdx.z;
    int tx = threadIdx.x;
    float gp = gp_[0], gc = gc_[0];
#pragma unroll
    for (int it = 0; it < 4; it++) {
        int ty = threadIdx.y + it * 8;
        int c = c0 + ty, pix = p0 + tx;
        int Y = pix >> 6, X = pix & 63;
        float v;
        if (c < 256) {
            float sy = Y * 0.5f - 0.25f, sx = X * 0.5f - 0.25f;
            int y0 = (int)floorf(sy); float fy = sy - y0;
            int x0 = (int)floorf(sx); float fx = sx - x0;
            int y1 = min(y0 + 1, 31); y0 = max(y0, 0);
            int x1 = min(x0 + 1, 31); x0 = max(x0, 0);
            const __half* p = g_O216 + c * 8192 + b * 1024;
            float v00 = __half2float(p[y0*32+x0]), v01 = __half2float(p[y0*32+x1]);
            float v10 = __half2float(p[y1*32+x0]), v11 = __half2float(p[y1*32+x1]);
            float u = (1.f - fy) * ((1.f - fx) * v00 + fx * v01)
                    + fy * ((1.f - fx) * v10 + fx * v11);
            v = xp_[((b * 256 + c) * 4096) + pix] + gp * u;
        } else {
            int g = c - 256;
            int pp = Y >> 1, ky = Y & 1, qq = X >> 1, kx = X & 1;
            float s = bt[g];
            int ob = (b * 2048 + g * 8) * 1024 + pp * 32 + qq;
#pragma unroll
            for (int i = 0; i < 8; i++)
                s += __half2float(g_oc16[ob + i * 1024]) * Wt[(g * 8 + i) * 4 + ky * 2 + kx];
            v = xc_[((b * 256 + g) * 4096) + pix] + gc * s;
        }
        t[ty][tx] = v;
    }
    __syncthreads();
#pragma unroll
    for (int it = 0; it < 4; it++) {
        int ty = threadIdx.y + it * 8;
        int pix = p0 + ty, c = c0 + tx;
        int Y = pix >> 6, X = pix & 63;
        long o = ((long)(b * 66 + 1 + Y) * 66 + 1 + X) * 512 + c;
        g_I316[o] = __float2half(t[tx][ty]);
    }
}

// ---------------- launch ----------------
static void* sym(const void* s) { void* p = nullptr; cudaGetSymbolAddress(&p, s); return p; }

extern "C" void kernel_launch(void* const* d_in, const int* in_sizes, int n_in,
                              void* d_out, int out_size) {
    const float *qkv_pos = (const float*)d_in[0], *qkv_cha = (const float*)d_in[1];
    const float *Wq_pos = (const float*)d_in[2], *bq_pos = (const float*)d_in[3];
    const float *Wk_pos = (const float*)d_in[4], *bk_pos = (const float*)d_in[5];
    const float *Wv_pos = (const float*)d_in[6], *bv_pos = (const float*)d_in[7];
    const float *Wo_pos = (const float*)d_in[8], *bo_pos = (const float*)d_in[9];
    const float *gamma_pos = (const float*)d_in[10];
    const float *Wq_cha = (const float*)d_in[11], *bq_cha = (const float*)d_in[12];
    const float *Wk_cha = (const float*)d_in[13], *bk_cha = (const float*)d_in[14];
    const float *Wv_cha = (const float*)d_in[15], *bv_cha = (const float*)d_in[16];
    const float *Wt_cha = (const float*)d_in[17], *bt_cha = (const float*)d_in[18];
    const float *gamma_cha = (const float*)d_in[19];
    const float *Wf = (const float*)d_in[20], *bf = (const float*)d_in[21];
    float* out = (float*)d_out;

    static cudaStream_t s1 = nullptr;
    static cudaEvent_t evF = nullptr, evJ = nullptr;
    if (!s1) {
        cudaStreamCreateWithFlags(&s1, cudaStreamNonBlocking);
        cudaEventCreateWithFlags(&evF, cudaEventDisableTiming);
        cudaEventCreateWithFlags(&evJ, cudaEventDisableTiming);
        cudaFuncSetAttribute(tgemm16<__half,true>, cudaFuncAttributeMaxDynamicSharedMemorySize, TSMEM16);
        cudaFuncSetAttribute(tgemm16<__half,false>, cudaFuncAttributeMaxDynamicSharedMemorySize, TSMEM16);
        cudaFuncSetAttribute(tgemm_conv16<5,256,34,false,__half>, cudaFuncAttributeMaxDynamicSharedMemorySize, TSMEM16);
        cudaFuncSetAttribute(tgemm_conv16<6,512,66,true,float>, cudaFuncAttributeMaxDynamicSharedMemorySize, TSMEM16);
        cudaFuncSetAttribute(tgemm_pv16, cudaFuncAttributeMaxDynamicSharedMemorySize, PVSMEM16);
    }

    __half *pW116 = (__half*)sym(g_W116), *pX116 = (__half*)sym(g_X116);
    __half *pP116 = (__half*)sym(g_P116);
    __half *pWo16 = (__half*)sym(g_Wo16), *pI216 = (__half*)sym(g_I216);
    __half *pWf16 = (__half*)sym(g_Wf16), *pI316 = (__half*)sym(g_I316);
    __half *pqc16 = (__half*)sym(g_qc16), *pkc16 = (__half*)sym(g_kc16);
    __half *pvT16 = (__half*)sym(g_vT16), *pPc16 = (__half*)sym(g_Pc16);
    __half *pSc16 = (__half*)sym(g_Sc16), *poc16 = (__half*)sym(g_oc16);
    __half *pO216 = (__half*)sym(g_O216);
    float *pb1 = (float*)sym(g_b1);

    // ---- fork: CHA branch + fusion prep on s1 ----
    cudaEventRecord(evF, 0);
    cudaStreamWaitEvent(s1, evF, 0);

    k_zero4<<<4356, 256, 0, s1>>>((float4*)pI316, 1115136);
    k_wrd16<<<4608, 256, 0, s1>>>(Wf, pWf16, 512);
    k_cha_proj<<<dim3(4, 256, 8), 256, 0, s1>>>(qkv_cha, Wq_cha, bq_cha, Wk_cha, bk_cha, Wv_cha, bv_cha);
    k_vcT<<<dim3(8, 32, 64), dim3(32, 8), 0, s1>>>();
    tgemm16<__half,false><<<dim3(2, 2, 64), 256, TSMEM16, s1>>>(pqc16, pkc16, pSc16, nullptr, 256, 1024, 262144L, 262144L, 65536L);
    k_cha_softmax<<<2048, 256, 0, s1>>>();
    tgemm16<__half,false><<<dim3(8, 2, 64), 256, TSMEM16, s1>>>(pPc16, pvT16, poc16, nullptr, 1024, 256, 65536L, 262144L, 262144L);
    cudaEventRecord(evJ, s1);

    // ---- POS branch on default stream ----
    k_pack_w1<<<1536, 256>>>(Wq_pos, bq_pos, Wk_pos, bk_pos, Wv_pos, bv_pos);
    k_im2col1<<<dim3(32, 256), dim3(32, 8)>>>(qkv_pos);
    k_zero4<<<578, 256>>>((float4*)pI216, 147968);
    tgemm16<__half,true><<<dim3(64, 3, 1), 256, TSMEM16>>>(pW116, pX116, pP116, pb1, 8192, 1024, 0, 0, 0);
    k_pos_attn<<<dim3(16, 8, 8), 256>>>();
    tgemm_pv16<<<dim3(4, 1, 64), 256, PVSMEM16>>>();
    k_o1t<<<dim3(32, 64), dim3(32, 8)>>>();
    k_wrd16<<<2304, 256>>>(Wo_pos, pWo16, 256);
    tgemm_conv16<5,256,34,false,__half><<<dim3(64, 2), 256, TSMEM16>>>(pWo16, pI216, pO216, bo_pos, 8192, 2304);

    // ---- join + fused residual/pack + fusion conv direct to out ----
    cudaStreamWaitEvent(0, evJ, 0);
    k_fusepack<<<dim3(16, 128, 8), dim3(32, 8)>>>(qkv_pos, qkv_cha, Wt_cha, bt_cha, gamma_pos, gamma_cha);
    tgemm_conv16<6,512,66,true,float><<<dim3(256, 2), 256, TSMEM16>>>(pWf16, pI316, out, bf, 32768, 4608);
}

// round 15
// speedup vs baseline: 1.1378x; 1.0244x over previous
#include <cuda_runtime.h>
#include <cuda_fp16.h>
#include <math.h>
#include <stdint.h>

#define Bz 8
#define BL 8192

__device__ __forceinline__ uint32_t smem_u32(const void* p) {
    uint32_t a;
    asm("{ .reg .u64 t; cvta.to.shared.u64 t, %1; cvt.u32.u64 %0, t; }" : "=r"(a) : "l"(p));
    return a;
}
__device__ __forceinline__ void cp16(uint32_t s, const void* g) {
    unsigned long long ga = (unsigned long long)__cvta_generic_to_global(g);
    asm volatile("cp.async.cg.shared.global [%0], [%1], 16;" :: "r"(s), "l"(ga));
}
__device__ __forceinline__ void ldsm4(uint32_t* r, uint32_t a) {
    asm volatile("ldmatrix.sync.aligned.m8n8.x4.shared.b16 {%0,%1,%2,%3}, [%4];"
                 : "=r"(r[0]), "=r"(r[1]), "=r"(r[2]), "=r"(r[3]) : "r"(a));
}
__device__ __forceinline__ void mmaf16(float* c, const uint32_t* a, const uint32_t* b) {
    asm volatile("mma.sync.aligned.m16n8k16.row.col.f32.f16.f16.f32 "
                 "{%0,%1,%2,%3}, {%4,%5,%6,%7}, {%8,%9}, {%0,%1,%2,%3};"
                 : "+f"(c[0]), "+f"(c[1]), "+f"(c[2]), "+f"(c[3])
                 : "r"(a[0]), "r"(a[1]), "r"(a[2]), "r"(a[3]), "r"(b[0]), "r"(b[1]));
}
__device__ __forceinline__ void stpair(float* C, long idx, float v0, float v1) {
    *(float2*)(C + idx) = make_float2(v0, v1);
}
__device__ __forceinline__ void stpair(__half* C, long idx, float v0, float v1) {
    *(__half2*)(C + idx) = __floats2half2_rn(v0, v1);
}

// ---------------- scratch ----------------
#define AL __align__(256)
__device__ AL __half g_W116[384*1024];
__device__ float g_b1[384];
__device__ AL __half g_X116[8192*1024];
__device__ AL __half g_P116[384*8192];
__device__ AL __half g_Pp16[(size_t)64*1024*1024];
__device__ AL __half g_vTp16[64*32*1024];
__device__ AL __half g_Wo16[256*2304];
__device__ AL __half g_I216[8*34*34*256];
__device__ AL __half g_O216[256*8192];
__device__ AL __half g_qc16[8*2048*1024], g_kc16[8*2048*1024];
__device__ AL __half g_vT16[64*1024*256];
__device__ AL __half g_Sc16[64*256*256];
__device__ AL __half g_Pc16[64*256*256];
__device__ AL __half g_oc16[8*2048*1024];
__device__ AL __half g_Wf16[256*4608];
__device__ AL __half g_I316[8*66*66*512];

#define PITCHB 80
#define TSZ 10240

// ========= fp16 single-term GEMM (128x128 tile, 8 warps, 2-stage) =========
#define STG16 20480
#define TSMEM16 (2*STG16)
template<typename TO, bool VOUT>
__global__ __launch_bounds__(256) void tgemm16(
    const __half* __restrict__ A, const __half* __restrict__ B,
    TO* __restrict__ C, const float* __restrict__ bias,
    int N, int K, long sA, long sB, long sC)
{
    extern __shared__ __align__(128) char smem_raw[];
    const uint32_t sb = smem_u32(smem_raw);
    const int tid = threadIdx.x, wid = tid >> 5, lane = tid & 31;
    const int wm = wid >> 2, wn = wid & 3;
    const int m0 = blockIdx.y * 128, n0 = blockIdx.x * 128;
    const __half* gp[2] = { A + (long)blockIdx.z * sA + (long)m0 * K,
                            B + (long)blockIdx.z * sB + (long)n0 * K };
    const int lg = lane >> 3, l8 = lane & 7;
    const int row_off = l8 + (lg & 1) * 8;
    const int kadd = (lg >> 1) * 8;
    const int rowA = wm * 64 + row_off;
    const int rowB = wn * 32 + row_off;

    float acc[4][4][4];
#pragma unroll
    for (int a = 0; a < 4; a++)
#pragma unroll
        for (int b = 0; b < 4; b++)
#pragma unroll
            for (int c = 0; c < 4; c++) acc[a][b][c] = 0.f;

    const int nch = K >> 5;
    auto load_stage = [&](int ch, int st) {
        uint32_t base = sb + st * STG16;
        int k0 = ch << 5;
#pragma unroll
        for (int j = 0; j < 4; j++) {
            int id = tid + j * 256;
            int t = id >> 9, w = id & 511;
            int row = w >> 2, c16 = (w & 3);
            cp16(base + t * TSZ + row * PITCHB + c16 * 16,
                 gp[t] + (long)row * K + k0 + c16 * 8);
        }
        asm volatile("cp.async.commit_group;" ::: "memory");
    };

    load_stage(0, 0);
    for (int i = 0; i < nch; i++) {
        int st = i & 1;
        if (i + 1 < nch) { load_stage(i + 1, st ^ 1);
            asm volatile("cp.async.wait_group 1;" ::: "memory");
        } else asm volatile("cp.async.wait_group 0;" ::: "memory");
        __syncthreads();
        uint32_t sA2 = sb + st * STG16, sB2 = sA2 + TSZ;
#pragma unroll
        for (int ks = 0; ks < 2; ks++) {
            uint32_t kb = (uint32_t)(ks * 16 + kadd) * 2;
            uint32_t bf[4][2];
#pragma unroll
            for (int p = 0; p < 2; p++) {
                uint32_t r[4];
                ldsm4(r, sB2 + (uint32_t)(rowB + p * 16) * PITCHB + kb);
                bf[p*2][0] = r[0]; bf[p*2][1] = r[2];
                bf[p*2+1][0] = r[1]; bf[p*2+1][1] = r[3];
            }
#pragma unroll
            for (int mt = 0; mt < 4; mt++) {
                uint32_t af[4];
                ldsm4(af, sA2 + (uint32_t)(rowA + mt * 16) * PITCHB + kb);
#pragma unroll
                for (int nt = 0; nt < 4; nt++) mmaf16(acc[mt][nt], af, bf[nt]);
            }
        }
        __syncthreads();
    }
    TO* Cb = C + (long)blockIdx.z * sC;
#pragma unroll
    for (int mt = 0; mt < 4; mt++) {
        int m = m0 + wm * 64 + mt * 16 + (lane >> 2);
        float b0 = bias ? bias[m] : 0.f;
        float b1 = bias ? bias[m + 8] : 0.f;
#pragma unroll
        for (int nt = 0; nt < 4; nt++) {
            int n = n0 + wn * 32 + nt * 8 + (lane & 3) * 2;
            float v0 = acc[mt][nt][0] + b0, v1 = acc[mt][nt][1] + b0;
            float v2 = acc[mt][nt][2] + b1, v3 = acc[mt][nt][3] + b1;
            if (VOUT && m >= 128) {
                int kk = n & 1023, bb = n >> 10;
                int z1 = bb * 8 + ((m - 128) >> 5), d1 = (m - 128) & 31;
                int z2 = bb * 8 + ((m - 120) >> 5), d2 = (m - 120) & 31;
                *(__half2*)(g_vTp16 + ((long)z1 * 32 + d1) * 1024 + kk) = __floats2half2_rn(v0, v1);
                *(__half2*)(g_vTp16 + ((long)z2 * 32 + d2) * 1024 + kk) = __floats2half2_rn(v2, v3);
            } else {
                stpair(Cb, (long)m * N + n, v0, v1);
                stpair(Cb, (long)(m + 8) * N + n, v2, v3);
            }
        }
    }
}

// ========= fp16 direct-conv GEMM (128x128 tile) =========
template<int LW, int CH, int PW, bool DIRECT, typename TO>
__global__ __launch_bounds__(256) void tgemm_conv16(
    const __half* __restrict__ A, const __half* __restrict__ I,
    TO* __restrict__ C, const float* __restrict__ bias, int N, int K)
{
    extern __shared__ __align__(128) char smem_raw[];
    const uint32_t sb = smem_u32(smem_raw);
    const int tid = threadIdx.x, wid = tid >> 5, lane = tid & 31;
    const int wm = wid >> 2, wn = wid & 3;
    const int m0 = blockIdx.y * 128, n0 = blockIdx.x * 128;
    const __half* pA = A + (long)m0 * K;
    constexpr int CPT = CH / 32;
    const int lg = lane >> 3, l8 = lane & 7;
    const int row_off = l8 + (lg & 1) * 8;
    const int kadd = (lg >> 1) * 8;
    const int rowA = wm * 64 + row_off;
    const int rowB = wn * 32 + row_off;

    float acc[4][4][4];
#pragma unroll
    for (int a = 0; a < 4; a++)
#pragma unroll
        for (int b = 0; b < 4; b++)
#pragma unroll
            for (int c = 0; c < 4; c++) acc[a][b][c] = 0.f;

    const int nch = K >> 5;
    auto load_stage = [&](int ch, int st) {
        uint32_t base = sb + st * STG16;
        int k0 = ch << 5;
        int tap = ch / CPT;
        int cc0 = (ch % CPT) << 5;
        int dyp = tap / 3, dxp = tap - dyp * 3;
#pragma unroll
        for (int j = 0; j < 4; j++) {
            int id = tid + j * 256;
            int t = id >> 9, w = id & 511;
            int row = w >> 2, c16 = (w & 3);
            uint32_t sa = base + t * TSZ + row * PITCHB + c16 * 16;
            if (t == 0) {
                cp16(sa, pA + (long)row * K + k0 + c16 * 8);
            } else {
                int n = n0 + row;
                int b = n >> (2 * LW);
                int pix = n & ((1 << (2 * LW)) - 1);
                int Y = pix >> LW, X = pix & ((1 << LW) - 1);
                long off = ((long)((b * PW + Y + dyp) * PW) + X + dxp) * CH + cc0 + c16 * 8;
                cp16(sa, I + off);
            }
        }
        asm volatile("cp.async.commit_group;" ::: "memory");
    };

    load_stage(0, 0);
    for (int i = 0; i < nch; i++) {
        int st = i & 1;
        if (i + 1 < nch) { load_stage(i + 1, st ^ 1);
            asm volatile("cp.async.wait_group 1;" ::: "memory");
        } else asm volatile("cp.async.wait_group 0;" ::: "memory");
        __syncthreads();
        uint32_t sA2 = sb + st * STG16, sB2 = sA2 + TSZ;
#pragma unroll
        for (int ks = 0; ks < 2; ks++) {
            uint32_t kb = (uint32_t)(ks * 16 + kadd) * 2;
            uint32_t bf[4][2];
#pragma unroll
            for (int p = 0; p < 2; p++) {
                uint32_t r[4];
                ldsm4(r, sB2 + (uint32_t)(rowB + p * 16) * PITCHB + kb);
                bf[p*2][0] = r[0]; bf[p*2][1] = r[2];
                bf[p*2+1][0] = r[1]; bf[p*2+1][1] = r[3];
            }
#pragma unroll
            for (int mt = 0; mt < 4; mt++) {
                uint32_t af[4];
                ldsm4(af, sA2 + (uint32_t)(rowA + mt * 16) * PITCHB + kb);
#pragma unroll
                for (int nt = 0; nt < 4; nt++) mmaf16(acc[mt][nt], af, bf[nt]);
            }
        }
        __syncthreads();
    }
#pragma unroll
    for (int mt = 0; mt < 4; mt++) {
        int m = m0 + wm * 64 + mt * 16 + (lane >> 2);
        float b0 = bias[m], b1 = bias[m + 8];
#pragma unroll
        for (int nt = 0; nt < 4; nt++) {
            int n = n0 + wn * 32 + nt * 8 + (lane & 3) * 2;
            float v0 = acc[mt][nt][0] + b0, v1 = acc[mt][nt][1] + b0;
            float v2 = acc[mt][nt][2] + b1, v3 = acc[mt][nt][3] + b1;
            if (DIRECT) {
                long base0 = ((long)(n >> 12) << 20) + (n & 4095);
                stpair(C, base0 + (long)m * 4096, v0, v1);
                stpair(C, base0 + (long)(m + 8) * 4096, v2, v3);
            } else {
                stpair(C, (long)m * N + n, v0, v1);
                stpair(C, (long)(m + 8) * N + n, v2, v3);
            }
        }
    }
}

// ========= fp16 PV GEMM — epilogue writes direct to padded ch-last I2 =========
#define PVATSZ 2560
#define PVBTSZ 20480
#define PVSTG16 (PVATSZ + PVBTSZ)
#define PVSMEM16 (2*PVSTG16)
__global__ __launch_bounds__(256) void tgemm_pv16()
{
    extern __shared__ __align__(128) char smem_raw[];
    const uint32_t sb = smem_u32(smem_raw);
    const int tid = threadIdx.x, wid = tid >> 5, lane = tid & 31;
    const int n0 = blockIdx.x * 256;
    const int z = blockIdx.z;
    const __half* pA = g_vTp16 + (long)z * 32768;
    const __half* pB = g_Pp16 + (size_t)z * 1048576;
    const int lg = lane >> 3, l8 = lane & 7;
    const int row_off = l8 + (lg & 1) * 8;
    const int kadd = (lg >> 1) * 8;
    const int rowB = wid * 32 + row_off;

    float acc[2][4][4];
#pragma unroll
    for (int a = 0; a < 2; a++)
#pragma unroll
        for (int b = 0; b < 4; b++)
#pragma unroll
            for (int c = 0; c < 4; c++) acc[a][b][c] = 0.f;

    auto load_stage = [&](int ch, int st) {
        uint32_t base = sb + st * PVSTG16;
        int k0 = ch << 5;
#pragma unroll
        for (int j = 0; j < 5; j++) {
            int id = tid + j * 256;
            if (id < 128) {
                int row = id >> 2, c16 = id & 3;
                cp16(base + row * PITCHB + c16 * 16, pA + (long)row * 1024 + k0 + c16 * 8);
            } else if (id < 1152) {
                int w = id - 128;
                int row = w >> 2, c16 = w & 3;
                cp16(base + PVATSZ + row * PITCHB + c16 * 16,
                     pB + (long)(n0 + row) * 1024 + k0 + c16 * 8);
            }
        }
        asm volatile("cp.async.commit_group;" ::: "memory");
    };

    load_stage(0, 0);
    for (int i = 0; i < 32; i++) {
        int st = i & 1;
        if (i + 1 < 32) { load_stage(i + 1, st ^ 1);
            asm volatile("cp.async.wait_group 1;" ::: "memory");
        } else asm volatile("cp.async.wait_group 0;" ::: "memory");
        __syncthreads();
        uint32_t sA2 = sb + st * PVSTG16, sB2 = sA2 + PVATSZ;
#pragma unroll
        for (int ks = 0; ks < 2; ks++) {
            uint32_t kb = (uint32_t)(ks * 16 + kadd) * 2;
            uint32_t bf[4][2];
#pragma unroll
            for (int p = 0; p < 2; p++) {
                uint32_t r[4];
                ldsm4(r, sB2 + (uint32_t)(rowB + p * 16) * PITCHB + kb);
                bf[p*2][0] = r[0]; bf[p*2][1] = r[2];
                bf[p*2+1][0] = r[1]; bf[p*2+1][1] = r[3];
            }
#pragma unroll
            for (int mt = 0; mt < 2; mt++) {
                uint32_t af[4];
                ldsm4(af, sA2 + (uint32_t)(row_off + mt * 16) * PITCHB + kb);
#pragma unroll
                for (int nt = 0; nt < 4; nt++) mmaf16(acc[mt][nt], af, bf[nt]);
            }
        }
        __syncthreads();
    }
    // epilogue: direct write into padded channels-last I2 image
    const int b = z >> 3, h = z & 7;
#pragma unroll
    for (int mt = 0; mt < 2; mt++) {
        int d = mt * 16 + (lane >> 2);
#pragma unroll
        for (int nt = 0; nt < 4; nt++) {
            int q = n0 + wid * 32 + nt * 8 + (lane & 3) * 2;
            int y = q >> 5, x = q & 31;
            long o = ((long)(b * 34 + 1 + y) * 34 + 1 + x) * 256 + h * 32 + d;
            g_I216[o]           = __float2half(acc[mt][nt][0]);
            g_I216[o + 256]     = __float2half(acc[mt][nt][1]);
            g_I216[o + 8]       = __float2half(acc[mt][nt][2]);
            g_I216[o + 264]     = __float2half(acc[mt][nt][3]);
        }
    }
}

// ---------------- reduce helpers ----------------
__device__ __forceinline__ float wmax(float v) {
#pragma unroll
    for (int o = 16; o; o >>= 1) v = fmaxf(v, __shfl_xor_sync(~0u, v, o));
    return v;
}
__device__ __forceinline__ float wsum(float v) {
#pragma unroll
    for (int o = 16; o; o >>= 1) v += __shfl_xor_sync(~0u, v, o);
    return v;
}

// ---------------- small kernels ----------------
__global__ void k_zero4(float4* p, int n4) {
    int i = blockIdx.x * 256 + threadIdx.x;
    if (i < n4) p[i] = make_float4(0.f, 0.f, 0.f, 0.f);
}
__global__ void k_wrd16(const float* __restrict__ W, __half* __restrict__ h, int CIN) {
    int idx = blockIdx.x * 256 + threadIdx.x;
    int K = CIN * 9;
    int oc = idx / K, rem = idx - oc * K;
    int cc = rem / 9, tap = rem - cc * 9;
    h[(long)oc * K + tap * CIN + cc] = __float2half(W[idx]);
}
__global__ void k_pack_w1(const float* __restrict__ Wq, const float* __restrict__ bq,
                          const float* __restrict__ Wk, const float* __restrict__ bk,
                          const float* __restrict__ Wv, const float* __restrict__ bv) {
    int idx = blockIdx.x * 256 + threadIdx.x;
    float v;
    if (idx < 65536) v = Wq[idx];
    else if (idx < 131072) v = Wk[idx - 65536];
    else v = Wv[idx - 131072];
    g_W116[idx] = __float2half(v);
    if (idx < 64) g_b1[idx] = bq[idx];
    else if (idx < 128) g_b1[idx] = bk[idx - 64];
    else if (idx < 384) g_b1[idx] = bv[idx - 128];
}
__global__ void k_im2col1(const float* __restrict__ x) {
    __shared__ float t[32][33];
    int k0 = blockIdx.x * 32, n0 = blockIdx.y * 32;
    int tx = threadIdx.x;
#pragma unroll
    for (int it = 0; it < 4; it++) {
        int ty = threadIdx.y + it * 8;
        int k = k0 + ty, n = n0 + tx;
        int c = k >> 2, ky = (k >> 1) & 1, kx = k & 1;
        int b = n >> 10, l = n & 1023, y = l >> 5, xq = l & 31;
        t[ty][tx] = x[(((b * 256 + c) * 64) + (y * 2 + ky)) * 64 + xq * 2 + kx];
    }
    __syncthreads();
#pragma unroll
    for (int it = 0; it < 4; it++) {
        int ty = threadIdx.y + it * 8;
        long o = (long)(n0 + ty) * 1024 + k0 + tx;
        g_X116[o] = __float2half(t[tx][ty]);
    }
}
__global__ void k_pos_attn() {
    __shared__ float Ks[8][1024];
    int b = blockIdx.z, h = blockIdx.y, tid = threadIdx.x;
    for (int idx = tid; idx < 8192; idx += 256) {
        int d = idx >> 10, k = idx & 1023;
        Ks[d][k] = __half2float(g_P116[(long)(64 + h * 8 + d) * BL + b * 1024 + k]);
    }
    __syncthreads();
    int warp = tid >> 5, lane = tid & 31;
    int qb = blockIdx.x * 64 + warp * 8;
#pragma unroll 1
    for (int qq = 0; qq < 8; qq++) {
        int q = qb + qq;
        float Q[8];
#pragma unroll
        for (int d = 0; d < 8; d++)
            Q[d] = __half2float(g_P116[(long)(h * 8 + d) * BL + b * 1024 + q]);
        float s[32], mx = -1e30f;
#pragma unroll
        for (int i = 0; i < 32; i++) {
            int k = i * 32 + lane;
            float sc = 0.f;
#pragma unroll
            for (int d = 0; d < 8; d++) sc += Q[d] * Ks[d][k];
            sc *= 0.35355339059327373f;
            s[i] = sc; mx = fmaxf(mx, sc);
        }
        mx = wmax(mx);
        float sum = 0.f;
#pragma unroll
        for (int i = 0; i < 32; i++) { float e = __expf(s[i] - mx); s[i] = e; sum += e; }
        float inv = 1.0f / wsum(sum);
        size_t ob = ((size_t)(b * 8 + h) * 1024 + q) * 1024 + lane;
#pragma unroll
        for (int i = 0; i < 32; i++) g_Pp16[ob + i * 32] = __float2half(s[i] * inv);
    }
}
__global__ void k_cha_proj(const float* __restrict__ x,
                           const float* __restrict__ Wq, const float* __restrict__ bq,
                           const float* __restrict__ Wk, const float* __restrict__ bk,
                           const float* __restrict__ Wv, const float* __restrict__ bv) {
    int l = blockIdx.x * 256 + threadIdx.x;
    int g = blockIdx.y, b = blockIdx.z;
    int i = l >> 5, j = l & 31;
    const float* xp = x + ((b * 256 + g) * 64) * 64;
    float x00 = xp[2*i*64 + 2*j], x01 = xp[2*i*64 + 2*j + 1];
    float x10 = xp[(2*i+1)*64 + 2*j], x11 = xp[(2*i+1)*64 + 2*j + 1];
    int base = (b * 2048 + g * 8) * 1024 + l;
    long vo = ((long)(b * 8 + (g >> 5))) * 262144 + (long)l * 256 + (g & 31) * 8;
#pragma unroll
    for (int h = 0; h < 8; h++) {
        int w = (g * 8 + h) * 4, o = base + h * 1024;
        float qv = Wq[w]*x00 + Wq[w+1]*x01 + Wq[w+2]*x10 + Wq[w+3]*x11 + bq[g*8+h];
        float kv = Wk[w]*x00 + Wk[w+1]*x01 + Wk[w+2]*x10 + Wk[w+3]*x11 + bk[g*8+h];
        float vv = Wv[w]*x00 + Wv[w+1]*x01 + Wv[w+2]*x10 + Wv[w+3]*x11 + bv[g*8+h];
        g_qc16[o] = __float2half(qv);
        g_kc16[o] = __float2half(kv);
        g_vT16[vo + h] = __float2half(vv);   // direct transposed V write
    }
}
__global__ void k_cha_softmax() {
    int row = blockIdx.x * 8 + (threadIdx.x >> 5);
    int lane = threadIdx.x & 31;
    const __half* r = g_Sc16 + (long)row * 256;
    float v[8], mx = -1e30f;
#pragma unroll
    for (int j = 0; j < 8; j++) {
        v[j] = __half2float(r[j * 32 + lane]) * 0.03125f;
        mx = fmaxf(mx, v[j]);
    }
    mx = wmax(mx);
    float sum = 0.f;
#pragma unroll
    for (int j = 0; j < 8; j++) { v[j] = __expf(v[j] - mx); sum += v[j]; }
    float inv = 1.0f / wsum(sum);
#pragma unroll
    for (int j = 0; j < 8; j++)
        g_Pc16[(long)row * 256 + j * 32 + lane] = __float2half(v[j] * inv);
}
__global__ void k_fusepack(const float* __restrict__ xp_, const float* __restrict__ xc_,
                           const float* __restrict__ Wt, const float* __restrict__ bt,
                           const float* __restrict__ gp_, const float* __restrict__ gc_) {
    __shared__ float t[32][33];
    int c0 = blockIdx.x * 32, p0 = blockIdx.y * 32, b = blockIdx.z;
    int tx = threadIdx.x;
    float gp = gp_[0], gc = gc_[0];
#pragma unroll
    for (int it = 0; it < 4; it++) {
        int ty = threadIdx.y + it * 8;
        int c = c0 + ty, pix = p0 + tx;
        int Y = pix >> 6, X = pix & 63;
        float v;
        if (c < 256) {
            float sy = Y * 0.5f - 0.25f, sx = X * 0.5f - 0.25f;
            int y0 = (int)floorf(sy); float fy = sy - y0;
            int x0 = (int)floorf(sx); float fx = sx - x0;
            int y1 = min(y0 + 1, 31); y0 = max(y0, 0);
            int x1 = min(x0 + 1, 31); x0 = max(x0, 0);
            const __half* p = g_O216 + c * 8192 + b * 1024;
            float v00 = __half2float(p[y0*32+x0]), v01 = __half2float(p[y0*32+x1]);
            float v10 = __half2float(p[y1*32+x0]), v11 = __half2float(p[y1*32+x1]);
            float u = (1.f - fy) * ((1.f - fx) * v00 + fx * v01)
                    + fy * ((1.f - fx) * v10 + fx * v11);
            v = xp_[((b * 256 + c) * 4096) + pix] + gp * u;
        } else {
            int g = c - 256;
            int pp = Y >> 1, ky = Y & 1, qq = X >> 1, kx = X & 1;
            float s = bt[g];
            int ob = (b * 2048 + g * 8) * 1024 + pp * 32 + qq;
#pragma unroll
            for (int i = 0; i < 8; i++)
                s += __half2float(g_oc16[ob + i * 1024]) * Wt[(g * 8 + i) * 4 + ky * 2 + kx];
            v = xc_[((b * 256 + g) * 4096) + pix] + gc * s;
        }
        t[ty][tx] = v;
    }
    __syncthreads();
#pragma unroll
    for (int it = 0; it < 4; it++) {
        int ty = threadIdx.y + it * 8;
        int pix = p0 + ty, c = c0 + tx;
        int Y = pix >> 6, X = pix & 63;
        long o = ((long)(b * 66 + 1 + Y) * 66 + 1 + X) * 512 + c;
        g_I316[o] = __float2half(t[tx][ty]);
    }
}

// ---------------- launch ----------------
static void* sym(const void* s) { void* p = nullptr; cudaGetSymbolAddress(&p, s); return p; }

extern "C" void kernel_launch(void* const* d_in, const int* in_sizes, int n_in,
                              void* d_out, int out_size) {
    const float *qkv_pos = (const float*)d_in[0], *qkv_cha = (const float*)d_in[1];
    const float *Wq_pos = (const float*)d_in[2], *bq_pos = (const float*)d_in[3];
    const float *Wk_pos = (const float*)d_in[4], *bk_pos = (const float*)d_in[5];
    const float *Wv_pos = (const float*)d_in[6], *bv_pos = (const float*)d_in[7];
    const float *Wo_pos = (const float*)d_in[8], *bo_pos = (const float*)d_in[9];
    const float *gamma_pos = (const float*)d_in[10];
    const float *Wq_cha = (const float*)d_in[11], *bq_cha = (const float*)d_in[12];
    const float *Wk_cha = (const float*)d_in[13], *bk_cha = (const float*)d_in[14];
    const float *Wv_cha = (const float*)d_in[15], *bv_cha = (const float*)d_in[16];
    const float *Wt_cha = (const float*)d_in[17], *bt_cha = (const float*)d_in[18];
    const float *gamma_cha = (const float*)d_in[19];
    const float *Wf = (const float*)d_in[20], *bf = (const float*)d_in[21];
    float* out = (float*)d_out;

    static cudaStream_t s1 = nullptr;
    static cudaEvent_t evF = nullptr, evJ = nullptr;
    if (!s1) {
        cudaStreamCreateWithFlags(&s1, cudaStreamNonBlocking);
        cudaEventCreateWithFlags(&evF, cudaEventDisableTiming);
        cudaEventCreateWithFlags(&evJ, cudaEventDisableTiming);
        cudaFuncSetAttribute(tgemm16<__half,true>, cudaFuncAttributeMaxDynamicSharedMemorySize, TSMEM16);
        cudaFuncSetAttribute(tgemm16<__half,false>, cudaFuncAttributeMaxDynamicSharedMemorySize, TSMEM16);
        cudaFuncSetAttribute(tgemm_conv16<5,256,34,false,__half>, cudaFuncAttributeMaxDynamicSharedMemorySize, TSMEM16);
        cudaFuncSetAttribute(tgemm_conv16<6,512,66,true,float>, cudaFuncAttributeMaxDynamicSharedMemorySize, TSMEM16);
        cudaFuncSetAttribute(tgemm_pv16, cudaFuncAttributeMaxDynamicSharedMemorySize, PVSMEM16);
    }

    __half *pW116 = (__half*)sym(g_W116), *pX116 = (__half*)sym(g_X116);
    __half *pP116 = (__half*)sym(g_P116);
    __half *pWo16 = (__half*)sym(g_Wo16), *pI216 = (__half*)sym(g_I216);
    __half *pWf16 = (__half*)sym(g_Wf16), *pI316 = (__half*)sym(g_I316);
    __half *pqc16 = (__half*)sym(g_qc16), *pkc16 = (__half*)sym(g_kc16);
    __half *pvT16 = (__half*)sym(g_vT16), *pPc16 = (__half*)sym(g_Pc16);
    __half *pSc16 = (__half*)sym(g_Sc16), *poc16 = (__half*)sym(g_oc16);
    __half *pO216 = (__half*)sym(g_O216);
    float *pb1 = (float*)sym(g_b1);

    // ---- fork: CHA branch + fusion prep on s1 ----
    cudaEventRecord(evF, 0);
    cudaStreamWaitEvent(s1, evF, 0);

    k_zero4<<<4356, 256, 0, s1>>>((float4*)pI316, 1115136);
    k_wrd16<<<4608, 256, 0, s1>>>(Wf, pWf16, 512);
    k_cha_proj<<<dim3(4, 256, 8), 256, 0, s1>>>(qkv_cha, Wq_cha, bq_cha, Wk_cha, bk_cha, Wv_cha, bv_cha);
    tgemm16<__half,false><<<dim3(2, 2, 64), 256, TSMEM16, s1>>>(pqc16, pkc16, pSc16, nullptr, 256, 1024, 262144L, 262144L, 65536L);
    k_cha_softmax<<<2048, 256, 0, s1>>>();
    tgemm16<__half,false><<<dim3(8, 2, 64), 256, TSMEM16, s1>>>(pPc16, pvT16, poc16, nullptr, 1024, 256, 65536L, 262144L, 262144L);
    cudaEventRecord(evJ, s1);

    // ---- POS branch on default stream ----
    k_pack_w1<<<1536, 256>>>(Wq_pos, bq_pos, Wk_pos, bk_pos, Wv_pos, bv_pos);
    k_im2col1<<<dim3(32, 256), dim3(32, 8)>>>(qkv_pos);
    k_zero4<<<578, 256>>>((float4*)pI216, 147968);
    k_wrd16<<<2304, 256>>>(Wo_pos, pWo16, 256);
    tgemm16<__half,true><<<dim3(64, 3, 1), 256, TSMEM16>>>(pW116, pX116, pP116, pb1, 8192, 1024, 0, 0, 0);
    k_pos_attn<<<dim3(16, 8, 8), 256>>>();
    tgemm_pv16<<<dim3(4, 1, 64), 256, PVSMEM16>>>();
    tgemm_conv16<5,256,34,false,__half><<<dim3(64, 2), 256, TSMEM16>>>(pWo16, pI216, pO216, bo_pos, 8192, 2304);

    // ---- join + fused residual/pack + fusion conv direct to out ----
    cudaStreamWaitEvent(0, evJ, 0);
    k_fusepack<<<dim3(16, 128, 8), dim3(32, 8)>>>(qkv_pos, qkv_cha, Wt_cha, bt_cha, gamma_pos, gamma_cha);
    tgemm_conv16<6,512,66,true,float><<<dim3(256, 2), 256, TSMEM16>>>(pWf16, pI316, out, bf, 32768, 4608);
}